// round 1
// baseline (speedup 1.0000x reference)
#include <cuda_runtime.h>
#include <cstdint>
#include <math.h>

typedef long long LL;

// ---------------- problem dims ----------------
constexpr int Bb   = 4;
constexpr int Ss   = 4096;
constexpr int Dm   = 2048;
constexpr int DFF  = 8192;
constexpr int Hh   = 16;
constexpr int HKV  = 8;
constexpr int DH   = 128;
constexpr int Rr   = 64;     // r_q == r_kv
constexpr int KD   = 64;     // kernel dim
constexpr int Ff   = 128;    // 2*KD
constexpr int Mtok = Bb * Ss;  // 16384

// ---------------- scratch (__device__ globals; no allocations allowed) ----------------
__device__ float g_cq  [(LL)Mtok * Rr];
__device__ float g_ckv [(LL)Mtok * Rr];
__device__ float g_q   [(LL)Mtok * Dm];
__device__ float g_k   [(LL)Mtok * (HKV * DH)];
__device__ float g_v   [(LL)Mtok * (HKV * DH)];
__device__ float g_phiq[(LL)Bb * Hh  * Ss * Ff];
__device__ float g_phik[(LL)Bb * HKV * Ss * Ff];
__device__ float g_kvpart[(LL)32 * 32 * Ff * DH];  // [bh2][split][f][d]
__device__ float g_zpart [(LL)32 * 32 * Ff];       // [bh2][split][f]
__device__ float g_kv64  [(LL)64 * Ff * DH];       // expanded to 64 query-head batches
__device__ float g_z     [(LL)32 * Ff];
__device__ float g_num [(LL)64 * Ss * Ff];         // [bh][s][d]
__device__ float g_attn[(LL)Mtok * Dm];            // [t][h*128+d]
__device__ float g_t1  [(LL)Mtok * Dm];            // residual sums
__device__ float g_h   [(LL)Mtok * Dm];            // LN1 output
__device__ float g_up  [(LL)Mtok * DFF];           // silu(up), then act (in-place mul)

// ---------------- generic tiled fp32 GEMM ----------------
// C[M,N] = A[M,K] @ B[K,N] (row-major, strides lda/ldb/ldc), optional batch via blockIdx.z.
// EPI: 0 none, 1 add D, 2 silu(acc), 3 mul D.
template<int BM, int BN, int BK, int TM, int TN, int EPI>
__global__ __launch_bounds__((BM/TM)*(BN/TN))
void gemm_kernel(const float* __restrict__ A, const float* __restrict__ B,
                 const float* __restrict__ D, float* __restrict__ C,
                 int K, int lda, int ldb, int ldc,
                 LL sA, LL sB, LL sC)
{
    constexpr int THREADS = (BM/TM)*(BN/TN);
    constexpr int NGRP = TN / 4;            // column groups of 4 (coalesced stores)
    __shared__ float As[BK][BM];
    __shared__ float Bs[BK][BN];

    const int tid = threadIdx.x;
    const int bm  = blockIdx.y * BM;
    const int bn  = blockIdx.x * BN;

    A += (LL)blockIdx.z * sA + (LL)bm * lda;
    B += (LL)blockIdx.z * sB + bn;
    C += (LL)blockIdx.z * sC;
    D += (LL)blockIdx.z * sC;

    const int tcol = tid % (BN/TN);
    const int trow = tid / (BN/TN);

    float acc[TM][TN];
    #pragma unroll
    for (int i = 0; i < TM; i++)
        #pragma unroll
        for (int j = 0; j < TN; j++) acc[i][j] = 0.f;

    constexpr int KF4 = BK / 4;
    const int a_r  = tid / KF4;
    const int a_c4 = (tid % KF4) * 4;
    constexpr int A_ROWS_PER = THREADS / KF4;
    constexpr int A_PASSES   = BM / A_ROWS_PER;
    constexpr int NF4 = BN / 4;
    const int b_r  = tid / NF4;
    const int b_c4 = (tid % NF4) * 4;
    constexpr int B_ROWS_PER = THREADS / NF4;
    constexpr int B_PASSES   = BK / B_ROWS_PER;

    for (int k0 = 0; k0 < K; k0 += BK) {
        #pragma unroll
        for (int p = 0; p < A_PASSES; p++) {
            int r = a_r + p * A_ROWS_PER;
            float4 va = *(const float4*)&A[(LL)r * lda + k0 + a_c4];
            As[a_c4 + 0][r] = va.x;
            As[a_c4 + 1][r] = va.y;
            As[a_c4 + 2][r] = va.z;
            As[a_c4 + 3][r] = va.w;
        }
        #pragma unroll
        for (int p = 0; p < B_PASSES; p++) {
            int r = b_r + p * B_ROWS_PER;
            *(float4*)&Bs[r][b_c4] = *(const float4*)&B[(LL)(k0 + r) * ldb + b_c4];
        }
        __syncthreads();
        #pragma unroll
        for (int kk = 0; kk < BK; kk++) {
            float ar[TM], br[TN];
            #pragma unroll
            for (int i = 0; i < TM; i += 4)
                *(float4*)&ar[i] = *(const float4*)&As[kk][trow * TM + i];
            #pragma unroll
            for (int g = 0; g < NGRP; g++)
                *(float4*)&br[4*g] = *(const float4*)&Bs[kk][tcol * 4 + g * (BN/2)];
            #pragma unroll
            for (int i = 0; i < TM; i++)
                #pragma unroll
                for (int j = 0; j < TN; j++)
                    acc[i][j] += ar[i] * br[j];
        }
        __syncthreads();
    }

    #pragma unroll
    for (int g = 0; g < NGRP; g++) {
        #pragma unroll
        for (int i = 0; i < TM; i++) {
            int r = bm + trow * TM + i;
            int c = bn + tcol * 4 + g * (BN/2);
            LL idx = (LL)r * ldc + c;
            float4 v;
            v.x = acc[i][4*g+0]; v.y = acc[i][4*g+1];
            v.z = acc[i][4*g+2]; v.w = acc[i][4*g+3];
            if (EPI == 1) {
                float4 d4 = *(const float4*)&D[idx];
                v.x += d4.x; v.y += d4.y; v.z += d4.z; v.w += d4.w;
            } else if (EPI == 2) {
                v.x = v.x / (1.f + expf(-v.x));
                v.y = v.y / (1.f + expf(-v.y));
                v.z = v.z / (1.f + expf(-v.z));
                v.w = v.w / (1.f + expf(-v.w));
            } else if (EPI == 3) {
                float4 d4 = *(const float4*)&D[idx];
                v.x *= d4.x; v.y *= d4.y; v.z *= d4.z; v.w *= d4.w;
            }
            *(float4*)&C[idx] = v;
        }
    }
}

// ---------------- phi: random Fourier features ----------------
// qk: [Mtok, estride], head h occupies cols [h*128, h*128+128)
// phi out: [b*nheads+h][Ss][Ff], cols 0..63 = cos, 64..127 = sin, scaled by 1/sqrt(KD)
__global__ __launch_bounds__(256)
void phi_kernel(const float* __restrict__ qk, const float* __restrict__ omega,
                float* __restrict__ phi, int nheads, int estride)
{
    __shared__ float om[DH][KD];   // 32 KB
    __shared__ float qs[16][DH];   //  8 KB
    const int h  = blockIdx.y;
    const int t0 = blockIdx.x * 16;
    const int tid = threadIdx.x;

    #pragma unroll
    for (int i = 0; i < 8; i++) {
        int fi = tid + i * 256;          // float4 index 0..2047
        int d  = fi >> 4;
        int c4 = (fi & 15) * 4;
        *(float4*)&om[d][c4] = *(const float4*)&omega[d * KD + c4];
    }
    #pragma unroll
    for (int i = 0; i < 2; i++) {
        int fi = tid + i * 256;          // 0..511
        int r  = fi >> 5;
        int c4 = (fi & 31) * 4;
        *(float4*)&qs[r][c4] = *(const float4*)&qk[(LL)(t0 + r) * estride + h * DH + c4];
    }
    __syncthreads();

    const int tl = tid >> 4;           // token 0..15
    const int kg = (tid & 15) * 4;     // 4 k-values per thread
    const int t  = t0 + tl;
    const int b  = t / Ss;
    const int sr = t - b * Ss;
    const LL base = ((LL)(b * nheads + h) * Ss + sr) * Ff;
    #pragma unroll
    for (int kk = 0; kk < 4; kk++) {
        int kc = kg + kk;
        float p = 0.f;
        #pragma unroll
        for (int d = 0; d < DH; d++) p += qs[tl][d] * om[d][kc];
        float sv, cv;
        sincosf(p, &sv, &cv);
        phi[base + kc]      = cv * 0.125f;
        phi[base + KD + kc] = sv * 0.125f;
    }
}

// ---------------- kv accumulation (deterministic split-K) ----------------
// kvpart[bh2][split][f][d] = sum over s in split of phik[bh2][s][f] * v[b, s, hk*128+d]
__global__ __launch_bounds__(256)
void kv_split_kernel(const float* __restrict__ phik, const float* __restrict__ v,
                     float* __restrict__ kvpart)
{
    const int split = blockIdx.x;
    const int bh2   = blockIdx.z;
    const int b  = bh2 >> 3;
    const int hk = bh2 & 7;
    const float* Pk = phik + (LL)bh2 * Ss * Ff;
    const float* V  = v + (LL)b * Ss * (HKV * DH) + hk * DH;
    __shared__ float As[16][128];
    __shared__ float Bs[16][128];
    const int tid  = threadIdx.x;
    const int tcol = tid & 15;
    const int trow = tid >> 4;
    const int lrow  = tid >> 5;         // 0..7
    const int lcol4 = (tid & 31) << 2;  // 0..124
    float acc[8][8];
    #pragma unroll
    for (int i = 0; i < 8; i++)
        #pragma unroll
        for (int j = 0; j < 8; j++) acc[i][j] = 0.f;

    const int s_base = split * 128;
    for (int ks = 0; ks < 8; ks++) {
        int s0 = s_base + ks * 16;
        #pragma unroll
        for (int p = 0; p < 2; p++) {
            int r = lrow + p * 8;
            *(float4*)&As[r][lcol4] = *(const float4*)&Pk[(LL)(s0 + r) * Ff + lcol4];
            *(float4*)&Bs[r][lcol4] = *(const float4*)&V[(LL)(s0 + r) * (HKV * DH) + lcol4];
        }
        __syncthreads();
        #pragma unroll
        for (int kk = 0; kk < 16; kk++) {
            float ar[8], br[8];
            *(float4*)&ar[0] = *(const float4*)&As[kk][trow * 8];
            *(float4*)&ar[4] = *(const float4*)&As[kk][trow * 8 + 4];
            *(float4*)&br[0] = *(const float4*)&Bs[kk][tcol * 8];
            *(float4*)&br[4] = *(const float4*)&Bs[kk][tcol * 8 + 4];
            #pragma unroll
            for (int i = 0; i < 8; i++)
                #pragma unroll
                for (int j = 0; j < 8; j++)
                    acc[i][j] += ar[i] * br[j];
        }
        __syncthreads();
    }
    float* out = kvpart + ((LL)bh2 * 32 + split) * (Ff * DH);
    #pragma unroll
    for (int i = 0; i < 8; i++)
        #pragma unroll
        for (int j = 0; j < 8; j++)
            out[(trow * 8 + i) * DH + tcol * 8 + j] = acc[i][j];
}

__global__ void z_split_kernel(const float* __restrict__ phik, float* __restrict__ zpart)
{
    const int split = blockIdx.x, bh2 = blockIdx.y, f = threadIdx.x;
    const float* P = phik + (LL)bh2 * Ss * Ff;
    const int s0 = split * 128;
    float s = 0.f;
    for (int i = 0; i < 128; i++) s += P[(LL)(s0 + i) * Ff + f];
    zpart[((LL)bh2 * 32 + split) * Ff + f] = s;
}

__global__ void kv_reduce_kernel(const float* __restrict__ kvpart, float* __restrict__ kv64)
{
    const int bh  = blockIdx.y;
    const int bh2 = (bh >> 4) * 8 + ((bh & 15) >> 1);
    const int idx = blockIdx.x * 128 + threadIdx.x;   // 0..16383
    const float* p = kvpart + (LL)bh2 * 32 * (Ff * DH) + idx;
    float s = 0.f;
    #pragma unroll
    for (int sp = 0; sp < 32; sp++) s += p[(LL)sp * (Ff * DH)];
    kv64[(LL)bh * (Ff * DH) + idx] = s;
}

__global__ void z_reduce_kernel(const float* __restrict__ zpart, float* __restrict__ z)
{
    const int bh2 = blockIdx.x, f = threadIdx.x;
    float s = 0.f;
    #pragma unroll
    for (int sp = 0; sp < 32; sp++) s += zpart[((LL)bh2 * 32 + sp) * Ff + f];
    z[bh2 * Ff + f] = s;
}

// ---------------- divide by denominator, write attn in [t, h*128+d] layout ----------------
__global__ __launch_bounds__(128)
void divide_kernel(const float* __restrict__ phiq, const float* __restrict__ z,
                   const float* __restrict__ num, float* __restrict__ attn)
{
    const int chunk = blockIdx.x, bh = blockIdx.y, tid = threadIdx.x;
    const int b = bh >> 4, h = bh & 15;
    const int bh2 = b * 8 + (h >> 1);
    __shared__ float zs[128];
    __shared__ float red[4];
    zs[tid] = z[bh2 * Ff + tid];
    __syncthreads();
    for (int i = 0; i < 32; i++) {
        int s = chunk * 32 + i;
        LL off = ((LL)bh * Ss + s) * Ff + tid;
        float pv = phiq[off] * zs[tid];
        #pragma unroll
        for (int o = 16; o > 0; o >>= 1) pv += __shfl_down_sync(0xffffffffu, pv, o);
        if ((tid & 31) == 0) red[tid >> 5] = pv;
        __syncthreads();
        float den = red[0] + red[1] + red[2] + red[3];
        attn[((LL)(b * Ss + s)) * Dm + h * DH + tid] = num[off] / (den + 1e-6f);
        __syncthreads();
    }
}

// ---------------- LayerNorm (one block per row of 2048) ----------------
__global__ __launch_bounds__(256)
void ln_kernel(const float* __restrict__ in, const float* __restrict__ gamma,
               const float* __restrict__ beta, float* __restrict__ out)
{
    const int row = blockIdx.x, tid = threadIdx.x;
    const float* p = in + (LL)row * Dm;
    float4 a = *(const float4*)&p[tid * 4];
    float4 b4 = *(const float4*)&p[1024 + tid * 4];
    float s = a.x + a.y + a.z + a.w + b4.x + b4.y + b4.z + b4.w;
    float q = a.x*a.x + a.y*a.y + a.z*a.z + a.w*a.w
            + b4.x*b4.x + b4.y*b4.y + b4.z*b4.z + b4.w*b4.w;
    __shared__ float rs[8], rq[8];
    #pragma unroll
    for (int o = 16; o > 0; o >>= 1) {
        s += __shfl_down_sync(0xffffffffu, s, o);
        q += __shfl_down_sync(0xffffffffu, q, o);
    }
    if ((tid & 31) == 0) { rs[tid >> 5] = s; rq[tid >> 5] = q; }
    __syncthreads();
    float S = 0.f, Q = 0.f;
    #pragma unroll
    for (int w = 0; w < 8; w++) { S += rs[w]; Q += rq[w]; }
    float mu = S / (float)Dm;
    float var = Q / (float)Dm - mu * mu;
    float rstd = rsqrtf(var + 1e-5f);

    float4 g0 = *(const float4*)&gamma[tid * 4];
    float4 bt0 = *(const float4*)&beta[tid * 4];
    float4 g1 = *(const float4*)&gamma[1024 + tid * 4];
    float4 bt1 = *(const float4*)&beta[1024 + tid * 4];
    float4 o0, o1;
    o0.x = (a.x - mu) * rstd * g0.x + bt0.x;
    o0.y = (a.y - mu) * rstd * g0.y + bt0.y;
    o0.z = (a.z - mu) * rstd * g0.z + bt0.z;
    o0.w = (a.w - mu) * rstd * g0.w + bt0.w;
    o1.x = (b4.x - mu) * rstd * g1.x + bt1.x;
    o1.y = (b4.y - mu) * rstd * g1.y + bt1.y;
    o1.z = (b4.z - mu) * rstd * g1.z + bt1.z;
    o1.w = (b4.w - mu) * rstd * g1.w + bt1.w;
    float* po = out + (LL)row * Dm;
    *(float4*)&po[tid * 4] = o0;
    *(float4*)&po[1024 + tid * 4] = o1;
}

// ---------------- launch ----------------
extern "C" void kernel_launch(void* const* d_in, const int* in_sizes, int n_in,
                              void* d_out, int out_size)
{
    const float* x      = (const float*)d_in[0];
    const float* W_dq   = (const float*)d_in[1];
    const float* W_uq   = (const float*)d_in[2];
    const float* W_dkv  = (const float*)d_in[3];
    const float* W_uk   = (const float*)d_in[4];
    const float* W_uv   = (const float*)d_in[5];
    const float* omega  = (const float*)d_in[6];
    const float* W_o    = (const float*)d_in[7];
    const float* ln1_g  = (const float*)d_in[8];
    const float* ln1_b  = (const float*)d_in[9];
    const float* gate_W = (const float*)d_in[10];
    const float* up_W   = (const float*)d_in[11];
    const float* down_W = (const float*)d_in[12];
    const float* ln2_g  = (const float*)d_in[13];
    const float* ln2_b  = (const float*)d_in[14];
    float* out = (float*)d_out;

    float *p_cq, *p_ckv, *p_q, *p_k, *p_v, *p_phiq, *p_phik;
    float *p_kvpart, *p_zpart, *p_kv64, *p_z, *p_num, *p_attn, *p_t1, *p_h, *p_up;
    cudaGetSymbolAddress((void**)&p_cq,     g_cq);
    cudaGetSymbolAddress((void**)&p_ckv,    g_ckv);
    cudaGetSymbolAddress((void**)&p_q,      g_q);
    cudaGetSymbolAddress((void**)&p_k,      g_k);
    cudaGetSymbolAddress((void**)&p_v,      g_v);
    cudaGetSymbolAddress((void**)&p_phiq,   g_phiq);
    cudaGetSymbolAddress((void**)&p_phik,   g_phik);
    cudaGetSymbolAddress((void**)&p_kvpart, g_kvpart);
    cudaGetSymbolAddress((void**)&p_zpart,  g_zpart);
    cudaGetSymbolAddress((void**)&p_kv64,   g_kv64);
    cudaGetSymbolAddress((void**)&p_z,      g_z);
    cudaGetSymbolAddress((void**)&p_num,    g_num);
    cudaGetSymbolAddress((void**)&p_attn,   g_attn);
    cudaGetSymbolAddress((void**)&p_t1,     g_t1);
    cudaGetSymbolAddress((void**)&p_h,      g_h);
    cudaGetSymbolAddress((void**)&p_up,     g_up);

    // 1) low-rank down-projections: c_q = x @ W_dq, c_kv = x @ W_dkv   [16384 x 64]
    gemm_kernel<128, 64, 16, 8, 4, 0><<<dim3(1, Mtok/128, 1), 256>>>(
        x, W_dq, nullptr, p_cq, Dm, Dm, Rr, Rr, 0, 0, 0);
    gemm_kernel<128, 64, 16, 8, 4, 0><<<dim3(1, Mtok/128, 1), 256>>>(
        x, W_dkv, nullptr, p_ckv, Dm, Dm, Rr, Rr, 0, 0, 0);

    // 2) up-projections: q [16384x2048], k/v [16384x1024]
    gemm_kernel<128, 128, 16, 8, 8, 0><<<dim3(Dm/128, Mtok/128, 1), 256>>>(
        p_cq, W_uq, nullptr, p_q, Rr, Rr, Dm, Dm, 0, 0, 0);
    gemm_kernel<128, 128, 16, 8, 8, 0><<<dim3((HKV*DH)/128, Mtok/128, 1), 256>>>(
        p_ckv, W_uk, nullptr, p_k, Rr, Rr, HKV*DH, HKV*DH, 0, 0, 0);
    gemm_kernel<128, 128, 16, 8, 8, 0><<<dim3((HKV*DH)/128, Mtok/128, 1), 256>>>(
        p_ckv, W_uv, nullptr, p_v, Rr, Rr, HKV*DH, HKV*DH, 0, 0, 0);

    // 3) random Fourier features
    phi_kernel<<<dim3(Mtok/16, Hh), 256>>>(p_q, omega, p_phiq, Hh, Dm);
    phi_kernel<<<dim3(Mtok/16, HKV), 256>>>(p_k, omega, p_phik, HKV, HKV*DH);

    // 4) kv = phi_k^T @ v and z = sum_s phi_k (deterministic split-K + reduce)
    kv_split_kernel<<<dim3(32, 1, 32), 256>>>(p_phik, p_v, p_kvpart);
    z_split_kernel<<<dim3(32, 32), 128>>>(p_phik, p_zpart);
    kv_reduce_kernel<<<dim3((Ff*DH)/128, 64), 128>>>(p_kvpart, p_kv64);
    z_reduce_kernel<<<32, 128>>>(p_zpart, p_z);

    // 5) num = phi_q @ kv (batched over 64 (b,h))
    gemm_kernel<128, 128, 16, 8, 8, 0><<<dim3(1, Ss/128, 64), 256>>>(
        p_phiq, p_kv64, nullptr, p_num, Ff, Ff, DH, DH,
        (LL)Ss * Ff, (LL)Ff * DH, (LL)Ss * DH);

    // 6) attn = num / (phi_q . z + 1e-6), laid out [t, h*128+d]
    divide_kernel<<<dim3(Ss/32, 64), 128>>>(p_phiq, p_z, p_num, p_attn);

    // 7) t1 = attn @ W_o + x
    gemm_kernel<128, 128, 16, 8, 8, 1><<<dim3(Dm/128, Mtok/128, 1), 256>>>(
        p_attn, W_o, x, p_t1, Dm, Dm, Dm, Dm, 0, 0, 0);

    // 8) h = LN1(t1)
    ln_kernel<<<Mtok, 256>>>(p_t1, ln1_g, ln1_b, p_h);

    // 9) up = silu(h @ up_W); act = (h @ gate_W) * up   (in-place)
    gemm_kernel<128, 128, 16, 8, 8, 2><<<dim3(DFF/128, Mtok/128, 1), 256>>>(
        p_h, up_W, nullptr, p_up, Dm, Dm, DFF, DFF, 0, 0, 0);
    gemm_kernel<128, 128, 16, 8, 8, 3><<<dim3(DFF/128, Mtok/128, 1), 256>>>(
        p_h, gate_W, p_up, p_up, Dm, Dm, DFF, DFF, 0, 0, 0);

    // 10) t1 = act @ down_W + h
    gemm_kernel<128, 128, 16, 8, 8, 1><<<dim3(Dm/128, Mtok/128, 1), 256>>>(
        p_up, down_W, p_h, p_t1, DFF, DFF, Dm, Dm, 0, 0, 0);

    // 11) out = LN2(t1)
    ln_kernel<<<Mtok, 256>>>(p_t1, ln2_g, ln2_b, out);
}

// round 2
// speedup vs baseline: 1.0005x; 1.0005x over previous
#include <cuda_runtime.h>
#include <cstdint>
#include <math.h>

typedef long long LL;

// ---------------- problem dims ----------------
constexpr int Bb   = 4;
constexpr int Ss   = 4096;
constexpr int Dm   = 2048;
constexpr int DFF  = 8192;
constexpr int Hh   = 16;
constexpr int HKV  = 8;
constexpr int DH   = 128;
constexpr int Rr   = 64;     // r_q == r_kv
constexpr int KD   = 64;     // kernel dim
constexpr int Ff   = 128;    // 2*KD
constexpr int Mtok = Bb * Ss;  // 16384

// ---------------- scratch (__device__ globals; no allocations allowed) ----------------
__device__ float g_cq  [(LL)Mtok * Rr];
__device__ float g_ckv [(LL)Mtok * Rr];
__device__ float g_q   [(LL)Mtok * Dm];
__device__ float g_k   [(LL)Mtok * (HKV * DH)];
__device__ float g_v   [(LL)Mtok * (HKV * DH)];
__device__ float g_phiq[(LL)Bb * Hh  * Ss * Ff];
__device__ float g_phik[(LL)Bb * HKV * Ss * Ff];
__device__ float g_kvpart[(LL)32 * 32 * Ff * DH];  // [bh2][split][f][d]
__device__ float g_zpart [(LL)32 * 32 * Ff];       // [bh2][split][f]
__device__ float g_kv64  [(LL)64 * Ff * DH];       // expanded to 64 query-head batches
__device__ float g_z     [(LL)32 * Ff];
__device__ float g_num [(LL)64 * Ss * Ff];         // [bh][s][d]
__device__ float g_attn[(LL)Mtok * Dm];            // [t][h*128+d]
__device__ float g_t1  [(LL)Mtok * Dm];            // residual sums
__device__ float g_h   [(LL)Mtok * Dm];            // LN1 output
__device__ float g_up  [(LL)Mtok * DFF];           // silu(up), then act (in-place mul)

// ---------------- generic tiled fp32 GEMM ----------------
// C[M,N] = A[M,K] @ B[K,N] (row-major, strides lda/ldb/ldc), optional batch via blockIdx.z.
// EPI: 0 none, 1 add D, 2 silu(acc), 3 mul D.
template<int BM, int BN, int BK, int TM, int TN, int EPI>
__global__ __launch_bounds__((BM/TM)*(BN/TN))
void gemm_kernel(const float* __restrict__ A, const float* __restrict__ B,
                 const float* __restrict__ D, float* __restrict__ C,
                 int K, int lda, int ldb, int ldc,
                 LL sA, LL sB, LL sC)
{
    constexpr int THREADS = (BM/TM)*(BN/TN);
    constexpr int NGRP = TN / 4;            // column groups of 4 (coalesced stores)
    __shared__ float As[BK][BM];
    __shared__ float Bs[BK][BN];

    const int tid = threadIdx.x;
    const int bm  = blockIdx.y * BM;
    const int bn  = blockIdx.x * BN;

    A += (LL)blockIdx.z * sA + (LL)bm * lda;
    B += (LL)blockIdx.z * sB + bn;
    C += (LL)blockIdx.z * sC;
    D += (LL)blockIdx.z * sC;

    const int tcol = tid % (BN/TN);
    const int trow = tid / (BN/TN);

    float acc[TM][TN];
    #pragma unroll
    for (int i = 0; i < TM; i++)
        #pragma unroll
        for (int j = 0; j < TN; j++) acc[i][j] = 0.f;

    constexpr int KF4 = BK / 4;
    const int a_r  = tid / KF4;
    const int a_c4 = (tid % KF4) * 4;
    constexpr int A_ROWS_PER = THREADS / KF4;
    constexpr int A_PASSES   = BM / A_ROWS_PER;
    constexpr int NF4 = BN / 4;
    const int b_r  = tid / NF4;
    const int b_c4 = (tid % NF4) * 4;
    constexpr int B_ROWS_PER = THREADS / NF4;
    constexpr int B_PASSES   = BK / B_ROWS_PER;

    for (int k0 = 0; k0 < K; k0 += BK) {
        #pragma unroll
        for (int p = 0; p < A_PASSES; p++) {
            int r = a_r + p * A_ROWS_PER;
            float4 va = *(const float4*)&A[(LL)r * lda + k0 + a_c4];
            As[a_c4 + 0][r] = va.x;
            As[a_c4 + 1][r] = va.y;
            As[a_c4 + 2][r] = va.z;
            As[a_c4 + 3][r] = va.w;
        }
        #pragma unroll
        for (int p = 0; p < B_PASSES; p++) {
            int r = b_r + p * B_ROWS_PER;
            *(float4*)&Bs[r][b_c4] = *(const float4*)&B[(LL)(k0 + r) * ldb + b_c4];
        }
        __syncthreads();
        #pragma unroll
        for (int kk = 0; kk < BK; kk++) {
            float ar[TM], br[TN];
            #pragma unroll
            for (int i = 0; i < TM; i += 4)
                *(float4*)&ar[i] = *(const float4*)&As[kk][trow * TM + i];
            #pragma unroll
            for (int g = 0; g < NGRP; g++)
                *(float4*)&br[4*g] = *(const float4*)&Bs[kk][tcol * 4 + g * (BN/2)];
            #pragma unroll
            for (int i = 0; i < TM; i++)
                #pragma unroll
                for (int j = 0; j < TN; j++)
                    acc[i][j] += ar[i] * br[j];
        }
        __syncthreads();
    }

    #pragma unroll
    for (int g = 0; g < NGRP; g++) {
        #pragma unroll
        for (int i = 0; i < TM; i++) {
            int r = bm + trow * TM + i;
            int c = bn + tcol * 4 + g * (BN/2);
            LL idx = (LL)r * ldc + c;
            float4 v;
            v.x = acc[i][4*g+0]; v.y = acc[i][4*g+1];
            v.z = acc[i][4*g+2]; v.w = acc[i][4*g+3];
            if (EPI == 1) {
                float4 d4 = *(const float4*)&D[idx];
                v.x += d4.x; v.y += d4.y; v.z += d4.z; v.w += d4.w;
            } else if (EPI == 2) {
                v.x = v.x / (1.f + expf(-v.x));
                v.y = v.y / (1.f + expf(-v.y));
                v.z = v.z / (1.f + expf(-v.z));
                v.w = v.w / (1.f + expf(-v.w));
            } else if (EPI == 3) {
                float4 d4 = *(const float4*)&D[idx];
                v.x *= d4.x; v.y *= d4.y; v.z *= d4.z; v.w *= d4.w;
            }
            *(float4*)&C[idx] = v;
        }
    }
}

// ---------------- phi: random Fourier features ----------------
// qk: [Mtok, estride], head h occupies cols [h*128, h*128+128)
// phi out: [b*nheads+h][Ss][Ff], cols 0..63 = cos, 64..127 = sin, scaled by 1/sqrt(KD)
__global__ __launch_bounds__(256)
void phi_kernel(const float* __restrict__ qk, const float* __restrict__ omega,
                float* __restrict__ phi, int nheads, int estride)
{
    __shared__ float om[DH][KD];   // 32 KB
    __shared__ float qs[16][DH];   //  8 KB
    const int h  = blockIdx.y;
    const int t0 = blockIdx.x * 16;
    const int tid = threadIdx.x;

    #pragma unroll
    for (int i = 0; i < 8; i++) {
        int fi = tid + i * 256;          // float4 index 0..2047
        int d  = fi >> 4;
        int c4 = (fi & 15) * 4;
        *(float4*)&om[d][c4] = *(const float4*)&omega[d * KD + c4];
    }
    #pragma unroll
    for (int i = 0; i < 2; i++) {
        int fi = tid + i * 256;          // 0..511
        int r  = fi >> 5;
        int c4 = (fi & 31) * 4;
        *(float4*)&qs[r][c4] = *(const float4*)&qk[(LL)(t0 + r) * estride + h * DH + c4];
    }
    __syncthreads();

    const int tl = tid >> 4;           // token 0..15
    const int kg = (tid & 15) * 4;     // 4 k-values per thread
    const int t  = t0 + tl;
    const int b  = t / Ss;
    const int sr = t - b * Ss;
    const LL base = ((LL)(b * nheads + h) * Ss + sr) * Ff;
    #pragma unroll
    for (int kk = 0; kk < 4; kk++) {
        int kc = kg + kk;
        float p = 0.f;
        #pragma unroll
        for (int d = 0; d < DH; d++) p += qs[tl][d] * om[d][kc];
        float sv, cv;
        sincosf(p, &sv, &cv);
        phi[base + kc]      = cv * 0.125f;
        phi[base + KD + kc] = sv * 0.125f;
    }
}

// ---------------- kv accumulation (deterministic split-K) ----------------
// kvpart[bh2][split][f][d] = sum over s in split of phik[bh2][s][f] * v[b, s, hk*128+d]
__global__ __launch_bounds__(256)
void kv_split_kernel(const float* __restrict__ phik, const float* __restrict__ v,
                     float* __restrict__ kvpart)
{
    const int split = blockIdx.x;
    const int bh2   = blockIdx.z;
    const int b  = bh2 >> 3;
    const int hk = bh2 & 7;
    const float* Pk = phik + (LL)bh2 * Ss * Ff;
    const float* V  = v + (LL)b * Ss * (HKV * DH) + hk * DH;
    __shared__ float As[16][128];
    __shared__ float Bs[16][128];
    const int tid  = threadIdx.x;
    const int tcol = tid & 15;
    const int trow = tid >> 4;
    const int lrow  = tid >> 5;         // 0..7
    const int lcol4 = (tid & 31) << 2;  // 0..124
    float acc[8][8];
    #pragma unroll
    for (int i = 0; i < 8; i++)
        #pragma unroll
        for (int j = 0; j < 8; j++) acc[i][j] = 0.f;

    const int s_base = split * 128;
    for (int ks = 0; ks < 8; ks++) {
        int s0 = s_base + ks * 16;
        #pragma unroll
        for (int p = 0; p < 2; p++) {
            int r = lrow + p * 8;
            *(float4*)&As[r][lcol4] = *(const float4*)&Pk[(LL)(s0 + r) * Ff + lcol4];
            *(float4*)&Bs[r][lcol4] = *(const float4*)&V[(LL)(s0 + r) * (HKV * DH) + lcol4];
        }
        __syncthreads();
        #pragma unroll
        for (int kk = 0; kk < 16; kk++) {
            float ar[8], br[8];
            *(float4*)&ar[0] = *(const float4*)&As[kk][trow * 8];
            *(float4*)&ar[4] = *(const float4*)&As[kk][trow * 8 + 4];
            *(float4*)&br[0] = *(const float4*)&Bs[kk][tcol * 8];
            *(float4*)&br[4] = *(const float4*)&Bs[kk][tcol * 8 + 4];
            #pragma unroll
            for (int i = 0; i < 8; i++)
                #pragma unroll
                for (int j = 0; j < 8; j++)
                    acc[i][j] += ar[i] * br[j];
        }
        __syncthreads();
    }
    float* out = kvpart + ((LL)bh2 * 32 + split) * (Ff * DH);
    #pragma unroll
    for (int i = 0; i < 8; i++)
        #pragma unroll
        for (int j = 0; j < 8; j++)
            out[(trow * 8 + i) * DH + tcol * 8 + j] = acc[i][j];
}

__global__ void z_split_kernel(const float* __restrict__ phik, float* __restrict__ zpart)
{
    const int split = blockIdx.x, bh2 = blockIdx.y, f = threadIdx.x;
    const float* P = phik + (LL)bh2 * Ss * Ff;
    const int s0 = split * 128;
    float s = 0.f;
    for (int i = 0; i < 128; i++) s += P[(LL)(s0 + i) * Ff + f];
    zpart[((LL)bh2 * 32 + split) * Ff + f] = s;
}

__global__ void kv_reduce_kernel(const float* __restrict__ kvpart, float* __restrict__ kv64)
{
    const int bh  = blockIdx.y;
    const int bh2 = (bh >> 4) * 8 + ((bh & 15) >> 1);
    const int idx = blockIdx.x * 128 + threadIdx.x;   // 0..16383
    const float* p = kvpart + (LL)bh2 * 32 * (Ff * DH) + idx;
    float s = 0.f;
    #pragma unroll
    for (int sp = 0; sp < 32; sp++) s += p[(LL)sp * (Ff * DH)];
    kv64[(LL)bh * (Ff * DH) + idx] = s;
}

__global__ void z_reduce_kernel(const float* __restrict__ zpart, float* __restrict__ z)
{
    const int bh2 = blockIdx.x, f = threadIdx.x;
    float s = 0.f;
    #pragma unroll
    for (int sp = 0; sp < 32; sp++) s += zpart[((LL)bh2 * 32 + sp) * Ff + f];
    z[bh2 * Ff + f] = s;
}

// ---------------- divide by denominator, write attn in [t, h*128+d] layout ----------------
__global__ __launch_bounds__(128)
void divide_kernel(const float* __restrict__ phiq, const float* __restrict__ z,
                   const float* __restrict__ num, float* __restrict__ attn)
{
    const int chunk = blockIdx.x, bh = blockIdx.y, tid = threadIdx.x;
    const int b = bh >> 4, h = bh & 15;
    const int bh2 = b * 8 + (h >> 1);
    __shared__ float zs[128];
    __shared__ float red[4];
    zs[tid] = z[bh2 * Ff + tid];
    __syncthreads();
    for (int i = 0; i < 32; i++) {
        int s = chunk * 32 + i;
        LL off = ((LL)bh * Ss + s) * Ff + tid;
        float pv = phiq[off] * zs[tid];
        #pragma unroll
        for (int o = 16; o > 0; o >>= 1) pv += __shfl_down_sync(0xffffffffu, pv, o);
        if ((tid & 31) == 0) red[tid >> 5] = pv;
        __syncthreads();
        float den = red[0] + red[1] + red[2] + red[3];
        attn[((LL)(b * Ss + s)) * Dm + h * DH + tid] = num[off] / (den + 1e-6f);
        __syncthreads();
    }
}

// ---------------- LayerNorm (one block per row of 2048) ----------------
__global__ __launch_bounds__(256)
void ln_kernel(const float* __restrict__ in, const float* __restrict__ gamma,
               const float* __restrict__ beta, float* __restrict__ out)
{
    const int row = blockIdx.x, tid = threadIdx.x;
    const float* p = in + (LL)row * Dm;
    float4 a = *(const float4*)&p[tid * 4];
    float4 b4 = *(const float4*)&p[1024 + tid * 4];
    float s = a.x + a.y + a.z + a.w + b4.x + b4.y + b4.z + b4.w;
    float q = a.x*a.x + a.y*a.y + a.z*a.z + a.w*a.w
            + b4.x*b4.x + b4.y*b4.y + b4.z*b4.z + b4.w*b4.w;
    __shared__ float rs[8], rq[8];
    #pragma unroll
    for (int o = 16; o > 0; o >>= 1) {
        s += __shfl_down_sync(0xffffffffu, s, o);
        q += __shfl_down_sync(0xffffffffu, q, o);
    }
    if ((tid & 31) == 0) { rs[tid >> 5] = s; rq[tid >> 5] = q; }
    __syncthreads();
    float S = 0.f, Q = 0.f;
    #pragma unroll
    for (int w = 0; w < 8; w++) { S += rs[w]; Q += rq[w]; }
    float mu = S / (float)Dm;
    float var = Q / (float)Dm - mu * mu;
    float rstd = rsqrtf(var + 1e-5f);

    float4 g0 = *(const float4*)&gamma[tid * 4];
    float4 bt0 = *(const float4*)&beta[tid * 4];
    float4 g1 = *(const float4*)&gamma[1024 + tid * 4];
    float4 bt1 = *(const float4*)&beta[1024 + tid * 4];
    float4 o0, o1;
    o0.x = (a.x - mu) * rstd * g0.x + bt0.x;
    o0.y = (a.y - mu) * rstd * g0.y + bt0.y;
    o0.z = (a.z - mu) * rstd * g0.z + bt0.z;
    o0.w = (a.w - mu) * rstd * g0.w + bt0.w;
    o1.x = (b4.x - mu) * rstd * g1.x + bt1.x;
    o1.y = (b4.y - mu) * rstd * g1.y + bt1.y;
    o1.z = (b4.z - mu) * rstd * g1.z + bt1.z;
    o1.w = (b4.w - mu) * rstd * g1.w + bt1.w;
    float* po = out + (LL)row * Dm;
    *(float4*)&po[tid * 4] = o0;
    *(float4*)&po[1024 + tid * 4] = o1;
}

// ---------------- launch ----------------
extern "C" void kernel_launch(void* const* d_in, const int* in_sizes, int n_in,
                              void* d_out, int out_size)
{
    const float* x      = (const float*)d_in[0];
    const float* W_dq   = (const float*)d_in[1];
    const float* W_uq   = (const float*)d_in[2];
    const float* W_dkv  = (const float*)d_in[3];
    const float* W_uk   = (const float*)d_in[4];
    const float* W_uv   = (const float*)d_in[5];
    const float* omega  = (const float*)d_in[6];
    const float* W_o    = (const float*)d_in[7];
    const float* ln1_g  = (const float*)d_in[8];
    const float* ln1_b  = (const float*)d_in[9];
    const float* gate_W = (const float*)d_in[10];
    const float* up_W   = (const float*)d_in[11];
    const float* down_W = (const float*)d_in[12];
    const float* ln2_g  = (const float*)d_in[13];
    const float* ln2_b  = (const float*)d_in[14];
    float* out = (float*)d_out;

    float *p_cq, *p_ckv, *p_q, *p_k, *p_v, *p_phiq, *p_phik;
    float *p_kvpart, *p_zpart, *p_kv64, *p_z, *p_num, *p_attn, *p_t1, *p_h, *p_up;
    cudaGetSymbolAddress((void**)&p_cq,     g_cq);
    cudaGetSymbolAddress((void**)&p_ckv,    g_ckv);
    cudaGetSymbolAddress((void**)&p_q,      g_q);
    cudaGetSymbolAddress((void**)&p_k,      g_k);
    cudaGetSymbolAddress((void**)&p_v,      g_v);
    cudaGetSymbolAddress((void**)&p_phiq,   g_phiq);
    cudaGetSymbolAddress((void**)&p_phik,   g_phik);
    cudaGetSymbolAddress((void**)&p_kvpart, g_kvpart);
    cudaGetSymbolAddress((void**)&p_zpart,  g_zpart);
    cudaGetSymbolAddress((void**)&p_kv64,   g_kv64);
    cudaGetSymbolAddress((void**)&p_z,      g_z);
    cudaGetSymbolAddress((void**)&p_num,    g_num);
    cudaGetSymbolAddress((void**)&p_attn,   g_attn);
    cudaGetSymbolAddress((void**)&p_t1,     g_t1);
    cudaGetSymbolAddress((void**)&p_h,      g_h);
    cudaGetSymbolAddress((void**)&p_up,     g_up);

    // 1) low-rank down-projections: c_q = x @ W_dq, c_kv = x @ W_dkv   [16384 x 64]
    gemm_kernel<128, 64, 16, 8, 4, 0><<<dim3(1, Mtok/128, 1), 256>>>(
        x, W_dq, nullptr, p_cq, Dm, Dm, Rr, Rr, 0, 0, 0);
    gemm_kernel<128, 64, 16, 8, 4, 0><<<dim3(1, Mtok/128, 1), 256>>>(
        x, W_dkv, nullptr, p_ckv, Dm, Dm, Rr, Rr, 0, 0, 0);

    // 2) up-projections: q [16384x2048], k/v [16384x1024]
    gemm_kernel<128, 128, 16, 8, 8, 0><<<dim3(Dm/128, Mtok/128, 1), 256>>>(
        p_cq, W_uq, nullptr, p_q, Rr, Rr, Dm, Dm, 0, 0, 0);
    gemm_kernel<128, 128, 16, 8, 8, 0><<<dim3((HKV*DH)/128, Mtok/128, 1), 256>>>(
        p_ckv, W_uk, nullptr, p_k, Rr, Rr, HKV*DH, HKV*DH, 0, 0, 0);
    gemm_kernel<128, 128, 16, 8, 8, 0><<<dim3((HKV*DH)/128, Mtok/128, 1), 256>>>(
        p_ckv, W_uv, nullptr, p_v, Rr, Rr, HKV*DH, HKV*DH, 0, 0, 0);

    // 3) random Fourier features
    phi_kernel<<<dim3(Mtok/16, Hh), 256>>>(p_q, omega, p_phiq, Hh, Dm);
    phi_kernel<<<dim3(Mtok/16, HKV), 256>>>(p_k, omega, p_phik, HKV, HKV*DH);

    // 4) kv = phi_k^T @ v and z = sum_s phi_k (deterministic split-K + reduce)
    kv_split_kernel<<<dim3(32, 1, 32), 256>>>(p_phik, p_v, p_kvpart);
    z_split_kernel<<<dim3(32, 32), 128>>>(p_phik, p_zpart);
    kv_reduce_kernel<<<dim3((Ff*DH)/128, 64), 128>>>(p_kvpart, p_kv64);
    z_reduce_kernel<<<32, 128>>>(p_zpart, p_z);

    // 5) num = phi_q @ kv (batched over 64 (b,h))
    gemm_kernel<128, 128, 16, 8, 8, 0><<<dim3(1, Ss/128, 64), 256>>>(
        p_phiq, p_kv64, nullptr, p_num, Ff, Ff, DH, DH,
        (LL)Ss * Ff, (LL)Ff * DH, (LL)Ss * DH);

    // 6) attn = num / (phi_q . z + 1e-6), laid out [t, h*128+d]
    divide_kernel<<<dim3(Ss/32, 64), 128>>>(p_phiq, p_z, p_num, p_attn);

    // 7) t1 = attn @ W_o + x
    gemm_kernel<128, 128, 16, 8, 8, 1><<<dim3(Dm/128, Mtok/128, 1), 256>>>(
        p_attn, W_o, x, p_t1, Dm, Dm, Dm, Dm, 0, 0, 0);

    // 8) h = LN1(t1)
    ln_kernel<<<Mtok, 256>>>(p_t1, ln1_g, ln1_b, p_h);

    // 9) up = silu(h @ up_W); act = (h @ gate_W) * up   (in-place)
    gemm_kernel<128, 128, 16, 8, 8, 2><<<dim3(DFF/128, Mtok/128, 1), 256>>>(
        p_h, up_W, nullptr, p_up, Dm, Dm, DFF, DFF, 0, 0, 0);
    gemm_kernel<128, 128, 16, 8, 8, 3><<<dim3(DFF/128, Mtok/128, 1), 256>>>(
        p_h, gate_W, p_up, p_up, Dm, Dm, DFF, DFF, 0, 0, 0);

    // 10) t1 = act @ down_W + h
    gemm_kernel<128, 128, 16, 8, 8, 1><<<dim3(Dm/128, Mtok/128, 1), 256>>>(
        p_up, down_W, p_h, p_t1, DFF, DFF, Dm, Dm, 0, 0, 0);

    // 11) out = LN2(t1)
    ln_kernel<<<Mtok, 256>>>(p_t1, ln2_g, ln2_b, out);
}

// round 6
// speedup vs baseline: 2.7860x; 2.7845x over previous
#include <cuda_runtime.h>
#include <cuda_fp16.h>
#include <cstdint>
#include <math.h>
typedef long long LL;

constexpr int Bb=4, Ss=4096, Dm=2048, DFF=8192, Hh=16, HKV=8, DH=128, Rr=64, KD=64, Ff=128;
constexpr int Mtok=Bb*Ss;

__device__ __forceinline__ uint32_t smem_u32(const void* p){uint32_t a;asm("{ .reg .u64 t; cvta.to.shared.u64 t, %1; cvt.u32.u64 %0, t; }":"=r"(a):"l"(p));return a;}
#define SW128(o) ((o) ^ (((o) >> 3) & 0x70))
#define CPA16(dst,src) asm volatile("cp.async.cg.shared.global [%0], [%1], 16;"::"r"(dst),"l"(src):"memory")
#define CPCOMMIT() asm volatile("cp.async.commit_group;":::"memory")
#define CPWAIT(n) asm volatile("cp.async.wait_group %0;"::"n"(n):"memory")
__device__ __forceinline__ void ldsm4(uint32_t* r, uint32_t a){
    asm volatile("ldmatrix.sync.aligned.m8n8.x4.shared.b16 {%0,%1,%2,%3}, [%4];"
        :"=r"(r[0]),"=r"(r[1]),"=r"(r[2]),"=r"(r[3]):"r"(a));}
__device__ __forceinline__ void ldsm2(uint32_t* r, uint32_t a){
    asm volatile("ldmatrix.sync.aligned.m8n8.x2.shared.b16 {%0,%1}, [%2];"
        :"=r"(r[0]),"=r"(r[1]):"r"(a));}
#define MMA(d,a,b) asm volatile("mma.sync.aligned.m16n8k16.row.col.f32.f16.f16.f32 {%0,%1,%2,%3},{%4,%5,%6,%7},{%8,%9},{%0,%1,%2,%3};" \
  :"+f"((d)[0]),"+f"((d)[1]),"+f"((d)[2]),"+f"((d)[3]) \
  :"r"((a)[0]),"r"((a)[1]),"r"((a)[2]),"r"((a)[3]),"r"((b)[0]),"r"((b)[1]))

__device__ __align__(16) __half g_xh[(LL)Mtok*Dm];
__device__ __align__(16) __half g_xl[(LL)Mtok*Dm];
__device__ __align__(16) __half g_cqh[(LL)Mtok*Rr];
__device__ __align__(16) __half g_cql[(LL)Mtok*Rr];
__device__ __align__(16) __half g_ckvh[(LL)Mtok*Rr];
__device__ __align__(16) __half g_ckvl[(LL)Mtok*Rr];
__device__ __align__(16) float g_q[(LL)Mtok*Dm];
__device__ __align__(16) float g_k[(LL)Mtok*HKV*DH];
__device__ __align__(16) float g_v[(LL)Mtok*HKV*DH];
__device__ __align__(16) __half g_phiqh[(LL)Mtok*Hh*Ff];
__device__ __align__(16) __half g_phiql[(LL)Mtok*Hh*Ff];
__device__ __align__(16) float g_phik[(LL)Mtok*HKV*Ff];
__device__ __align__(16) float g_kvpart[(LL)32*32*Ff*DH];
__device__ __align__(16) float g_zpart[(LL)32*32*Ff];
__device__ __align__(16) __half g_kvTh[(LL)64*DH*Ff];
__device__ __align__(16) __half g_kvTl[(LL)64*DH*Ff];
__device__ __align__(16) float g_z[(LL)32*Ff];
__device__ __align__(16) float g_num[(LL)64*Ss*Ff];
__device__ __align__(16) __half g_attnh[(LL)Mtok*Dm];
__device__ __align__(16) __half g_attnl[(LL)Mtok*Dm];
__device__ __align__(16) float g_t1[(LL)Mtok*Dm];
__device__ __align__(16) float g_h[(LL)Mtok*Dm];
__device__ __align__(16) __half g_hh[(LL)Mtok*Dm];
__device__ __align__(16) __half g_hl[(LL)Mtok*Dm];
__device__ __align__(16) float g_silu[(LL)Mtok*DFF];
__device__ __align__(16) __half g_acth[(LL)Mtok*DFF];
__device__ __align__(16) __half g_actl[(LL)Mtok*DFF];
__device__ __align__(16) __half g_w1h[(LL)Rr*Dm];
__device__ __align__(16) __half g_w1l[(LL)Rr*Dm];
__device__ __align__(16) __half g_w2h[(LL)Rr*Dm];
__device__ __align__(16) __half g_w2l[(LL)Rr*Dm];
__device__ __align__(16) __half g_w3h[(LL)Dm*Rr];
__device__ __align__(16) __half g_w3l[(LL)Dm*Rr];
__device__ __align__(16) __half g_w4h[(LL)HKV*DH*Rr];
__device__ __align__(16) __half g_w4l[(LL)HKV*DH*Rr];
__device__ __align__(16) __half g_w5h[(LL)HKV*DH*Rr];
__device__ __align__(16) __half g_w5l[(LL)HKV*DH*Rr];
__device__ __align__(16) __half g_w6h[(LL)Dm*Dm];
__device__ __align__(16) __half g_w6l[(LL)Dm*Dm];
__device__ __align__(16) __half g_w7h[(LL)DFF*Dm];
__device__ __align__(16) __half g_w7l[(LL)DFF*Dm];
__device__ __align__(16) __half g_w8h[(LL)DFF*Dm];
__device__ __align__(16) __half g_w8l[(LL)DFF*Dm];
__device__ __align__(16) __half g_w9h[(LL)Dm*DFF];
__device__ __align__(16) __half g_w9l[(LL)Dm*DFF];

__device__ __forceinline__ void split2(float v, __half* ph, __half* pl){
    __half h=__float2half_rn(v); *ph=h; *pl=__float2half_rn(v-__half2float(h));}

__global__ __launch_bounds__(256) void convT(const float* __restrict__ W, __half* __restrict__ Wh, __half* __restrict__ Wl, int K, int N){
    __shared__ float t[32][33];
    int tx=threadIdx.x, ty=threadIdx.y, k0=blockIdx.y*32, n0=blockIdx.x*32;
    #pragma unroll
    for(int i=0;i<4;i++){int r=ty+i*8; t[r][tx]=W[(LL)(k0+r)*N+n0+tx];}
    __syncthreads();
    #pragma unroll
    for(int i=0;i<4;i++){int r=ty+i*8; LL o=(LL)(n0+r)*K+k0+tx; split2(t[tx][r],&Wh[o],&Wl[o]);}
}
__global__ __launch_bounds__(256) void convE(const float* __restrict__ X, __half* __restrict__ Xh, __half* __restrict__ Xl, LL n){
    LL i=((LL)blockIdx.x*256+threadIdx.x)*4; if(i>=n) return;
    float4 v=*(const float4*)&X[i];
    split2(v.x,&Xh[i],&Xl[i]); split2(v.y,&Xh[i+1],&Xl[i+1]); split2(v.z,&Xh[i+2],&Xl[i+2]); split2(v.w,&Xh[i+3],&Xl[i+3]);
}

// C[M,N] = A[M,K] @ B[N,K]^T, fp16 hi/lo, fp32 accum via 3 HMMAs per fragment pair.
template<int BN,int EPI,int OUTM>
__global__ __launch_bounds__(256) void tgemm(
    const __half* __restrict__ Ah, const __half* __restrict__ Al,
    const __half* __restrict__ Bh, const __half* __restrict__ Bl,
    const float* __restrict__ D, float* __restrict__ C,
    __half* __restrict__ Chi, __half* __restrict__ Clo,
    int K, int ldc, LL sA, LL sB, LL sC)
{
    extern __shared__ char smem[];
    const uint32_t sbase=smem_u32(smem);
    const int tid=threadIdx.x, wid=tid>>5, lane=tid&31;
    constexpr int ABYT=16384, BBYT=BN*128, BUF=2*ABYT+2*BBYT;
    const int bm=blockIdx.y*128, bn=blockIdx.x*BN, bz=blockIdx.z;
    const __half* APh=Ah+(LL)bz*sA+(LL)bm*K;
    const __half* APl=Al+(LL)bz*sA+(LL)bm*K;
    const __half* BPh=Bh+(LL)bz*sB+(LL)bn*K;
    const __half* BPl=Bl+(LL)bz*sB+(LL)bn*K;
    const int KT=K>>6;

    auto load=[&](int kt,int buf){
        uint32_t base=sbase+buf*BUF;
        const LL ko=(LL)kt*64;
        #pragma unroll
        for(int i=0;i<4;i++){
            int c=tid+i*256, r=c>>3, ch=c&7; uint32_t sw=SW128(r*128+ch*16);
            CPA16(base+sw,      APh+(LL)r*K+ko+ch*8);
            CPA16(base+ABYT+sw, APl+(LL)r*K+ko+ch*8);
        }
        #pragma unroll
        for(int i=0;i<BN/32;i++){
            int c=tid+i*256, r=c>>3, ch=c&7; uint32_t sw=SW128(r*128+ch*16);
            CPA16(base+2*ABYT+sw,      BPh+(LL)r*K+ko+ch*8);
            CPA16(base+2*ABYT+BBYT+sw, BPl+(LL)r*K+ko+ch*8);
        }
    };

    constexpr int WN=BN/4, NF=WN/8;
    const int g=lane>>2, tg=lane&3, wm=wid&1, wn=wid>>1;
    float acc[4][NF][4];
    #pragma unroll
    for(int i=0;i<4;i++)
        #pragma unroll
        for(int j=0;j<NF;j++){acc[i][j][0]=0.f;acc[i][j][1]=0.f;acc[i][j][2]=0.f;acc[i][j][3]=0.f;}

    // ldmatrix per-lane address pieces
    const int aquad=lane>>3, alr=lane&7;
    const int arow = wm*64 + ((aquad&1)<<3) + alr;      // + mf*16
    const int acol = (aquad>>1)<<4;                      // + ks*32
    const int brow = wn*WN + (lane&7);                   // + nf*8
    const int bcol = ((lane>>3)&1)<<4;                   // + ks*32

    load(0,0); CPCOMMIT();
    for(int kt=0;kt<KT;kt++){
        if(kt+1<KT){ load(kt+1,(kt+1)&1); CPCOMMIT(); CPWAIT(1); }
        else { CPWAIT(0); }
        __syncthreads();
        const uint32_t cbase=sbase+(kt&1)*BUF;
        #pragma unroll
        for(int ks=0;ks<4;ks++){
            uint32_t ahf[4][4], alf[4][4], bhf[NF][2], blf[NF][2];
            #pragma unroll
            for(int mf=0;mf<4;mf++){
                uint32_t ad=cbase+SW128((arow+mf*16)*128 + ks*32+acol);
                ldsm4(ahf[mf], ad);
                ldsm4(alf[mf], ad+ABYT);
            }
            #pragma unroll
            for(int nf=0;nf<NF;nf++){
                uint32_t bd=cbase+2*ABYT+SW128((brow+nf*8)*128 + ks*32+bcol);
                ldsm2(bhf[nf], bd);
                ldsm2(blf[nf], bd+BBYT);
            }
            #pragma unroll
            for(int mf=0;mf<4;mf++)
                #pragma unroll
                for(int nf=0;nf<NF;nf++){
                    MMA(acc[mf][nf], ahf[mf], bhf[nf]);
                    MMA(acc[mf][nf], ahf[mf], blf[nf]);
                    MMA(acc[mf][nf], alf[mf], bhf[nf]);
                }
        }
        __syncthreads();
    }

    #pragma unroll
    for(int mf=0;mf<4;mf++)
        #pragma unroll
        for(int nf=0;nf<NF;nf++)
            #pragma unroll
            for(int hr=0;hr<2;hr++){
                int r=bm+wm*64+mf*16+g+hr*8;
                int c=bn+wn*WN+nf*8+tg*2;
                LL idx=(LL)bz*sC+(LL)r*ldc+c;
                float v0=acc[mf][nf][hr*2], v1=acc[mf][nf][hr*2+1];
                if(EPI==1){float2 d2=*(const float2*)&D[idx]; v0+=d2.x; v1+=d2.y;}
                else if(EPI==2){v0=v0/(1.f+expf(-v0)); v1=v1/(1.f+expf(-v1));}
                else if(EPI==3){float2 d2=*(const float2*)&D[idx]; v0*=d2.x; v1*=d2.y;}
                if(OUTM&1){float2 o2; o2.x=v0; o2.y=v1; *(float2*)&C[idx]=o2;}
                if(OUTM&2){
                    __half h0=__float2half_rn(v0), h1=__float2half_rn(v1);
                    *(__half2*)&Chi[idx]=__halves2half2(h0,h1);
                    *(__half2*)&Clo[idx]=__halves2half2(
                        __float2half_rn(v0-__half2float(h0)), __float2half_rn(v1-__half2float(h1)));
                }
            }
}

template<bool HILO>
__global__ __launch_bounds__(256) void phi_kernel(const float* __restrict__ qk, const float* __restrict__ omega,
    float* __restrict__ phi, __half* __restrict__ ph, __half* __restrict__ pl, int nheads, int estride)
{
    __shared__ float om[DH][KD]; __shared__ float qs[16][DH];
    const int h=blockIdx.y, t0=blockIdx.x*16, tid=threadIdx.x;
    #pragma unroll
    for(int i=0;i<8;i++){int fi=tid+i*256,d=fi>>4,c4=(fi&15)*4;*(float4*)&om[d][c4]=*(const float4*)&omega[d*KD+c4];}
    #pragma unroll
    for(int i=0;i<2;i++){int fi=tid+i*256,r=fi>>5,c4=(fi&31)*4;*(float4*)&qs[r][c4]=*(const float4*)&qk[(LL)(t0+r)*estride+h*DH+c4];}
    __syncthreads();
    const int tl=tid>>4, kg=(tid&15)*4, t=t0+tl, b=t/Ss, sr=t-b*Ss;
    const LL base=((LL)(b*nheads+h)*Ss+sr)*Ff;
    #pragma unroll
    for(int kk=0;kk<4;kk++){
        int kc=kg+kk; float pr=0.f;
        #pragma unroll
        for(int d=0;d<DH;d++) pr+=qs[tl][d]*om[d][kc];
        float sv,cv; sincosf(pr,&sv,&cv);
        float vc=cv*0.125f, vs=sv*0.125f;
        if(HILO){split2(vc,&ph[base+kc],&pl[base+kc]); split2(vs,&ph[base+KD+kc],&pl[base+KD+kc]);}
        else{phi[base+kc]=vc; phi[base+KD+kc]=vs;}
    }
}

__global__ __launch_bounds__(256) void kv_split(const float* __restrict__ phik, const float* __restrict__ v, float* __restrict__ kvpart){
    const int split=blockIdx.x, bh2=blockIdx.z, b=bh2>>3, hk=bh2&7;
    const float* Pk=phik+(LL)bh2*Ss*Ff;
    const float* V=v+(LL)b*Ss*(HKV*DH)+hk*DH;
    __shared__ float As[16][128]; __shared__ float Bs[16][128];
    const int tid=threadIdx.x, tc=tid&15, tr=tid>>4, lr=tid>>5, lc=(tid&31)<<2;
    float acc[8][8];
    #pragma unroll
    for(int i=0;i<8;i++)
        #pragma unroll
        for(int j=0;j<8;j++) acc[i][j]=0.f;
    for(int ks=0;ks<8;ks++){
        int s0=split*128+ks*16;
        #pragma unroll
        for(int pp=0;pp<2;pp++){int r=lr+pp*8;
            *(float4*)&As[r][lc]=*(const float4*)&Pk[(LL)(s0+r)*Ff+lc];
            *(float4*)&Bs[r][lc]=*(const float4*)&V[(LL)(s0+r)*(HKV*DH)+lc];}
        __syncthreads();
        #pragma unroll
        for(int kk=0;kk<16;kk++){
            float ar[8],br[8];
            *(float4*)&ar[0]=*(const float4*)&As[kk][tr*8]; *(float4*)&ar[4]=*(const float4*)&As[kk][tr*8+4];
            *(float4*)&br[0]=*(const float4*)&Bs[kk][tc*8]; *(float4*)&br[4]=*(const float4*)&Bs[kk][tc*8+4];
            #pragma unroll
            for(int i=0;i<8;i++)
                #pragma unroll
                for(int j=0;j<8;j++) acc[i][j]+=ar[i]*br[j];
        }
        __syncthreads();
    }
    float* o=kvpart+((LL)bh2*32+split)*(Ff*DH);
    #pragma unroll
    for(int i=0;i<8;i++)
        #pragma unroll
        for(int j=0;j<8;j++) o[(tr*8+i)*DH+tc*8+j]=acc[i][j];
}
__global__ void z_split(const float* __restrict__ phik, float* __restrict__ zp){
    const int split=blockIdx.x, bh2=blockIdx.y, f=threadIdx.x;
    const float* P=phik+(LL)bh2*Ss*Ff; float s=0.f;
    for(int i=0;i<128;i++) s+=P[(LL)(split*128+i)*Ff+f];
    zp[((LL)bh2*32+split)*Ff+f]=s;
}
__global__ void kv_reduce(const float* __restrict__ kvp, __half* __restrict__ kvh, __half* __restrict__ kvl){
    const int bh=blockIdx.y, bh2=(bh>>4)*8+((bh&15)>>1);
    const int idx=blockIdx.x*128+threadIdx.x;
    const float* p=kvp+(LL)bh2*32*(Ff*DH)+idx;
    float s=0.f;
    #pragma unroll
    for(int sp=0;sp<32;sp++) s+=p[(LL)sp*(Ff*DH)];
    int f=idx>>7, d=idx&127;
    LL o=(LL)bh*(DH*Ff)+(LL)d*Ff+f;
    split2(s,&kvh[o],&kvl[o]);
}
__global__ void z_reduce(const float* __restrict__ zp, float* __restrict__ z){
    const int bh2=blockIdx.x, f=threadIdx.x; float s=0.f;
    #pragma unroll
    for(int sp=0;sp<32;sp++) s+=zp[((LL)bh2*32+sp)*Ff+f];
    z[bh2*Ff+f]=s;
}
__global__ __launch_bounds__(128) void divide_k(const __half* __restrict__ pqh, const __half* __restrict__ pql,
    const float* __restrict__ z, const float* __restrict__ num, __half* __restrict__ ah, __half* __restrict__ al){
    const int chunk=blockIdx.x, bh=blockIdx.y, tid=threadIdx.x;
    const int b=bh>>4, h=bh&15, bh2=b*8+(h>>1);
    __shared__ float zs[128]; __shared__ float red[4];
    zs[tid]=z[bh2*Ff+tid]; __syncthreads();
    for(int i=0;i<32;i++){
        int s=chunk*32+i;
        LL off=((LL)bh*Ss+s)*Ff+tid;
        float pq=__half2float(pqh[off])+__half2float(pql[off]);
        float pv=pq*zs[tid];
        #pragma unroll
        for(int o=16;o>0;o>>=1) pv+=__shfl_down_sync(0xffffffffu,pv,o);
        if((tid&31)==0) red[tid>>5]=pv;
        __syncthreads();
        float den=red[0]+red[1]+red[2]+red[3];
        float a=num[off]/(den+1e-6f);
        LL oo=((LL)(b*Ss+s))*Dm+h*DH+tid;
        split2(a,&ah[oo],&al[oo]);
        __syncthreads();
    }
}
template<bool HILO>
__global__ __launch_bounds__(256) void ln_k(const float* __restrict__ in, const float* __restrict__ g, const float* __restrict__ be,
    float* __restrict__ out, __half* __restrict__ oh, __half* __restrict__ ol){
    const int row=blockIdx.x, tid=threadIdx.x;
    const float* p=in+(LL)row*Dm;
    float4 a=*(const float4*)&p[tid*4], b4=*(const float4*)&p[1024+tid*4];
    float s=a.x+a.y+a.z+a.w+b4.x+b4.y+b4.z+b4.w;
    float q=a.x*a.x+a.y*a.y+a.z*a.z+a.w*a.w+b4.x*b4.x+b4.y*b4.y+b4.z*b4.z+b4.w*b4.w;
    __shared__ float rs[8], rq[8];
    #pragma unroll
    for(int o=16;o>0;o>>=1){s+=__shfl_down_sync(0xffffffffu,s,o);q+=__shfl_down_sync(0xffffffffu,q,o);}
    if((tid&31)==0){rs[tid>>5]=s;rq[tid>>5]=q;}
    __syncthreads();
    float S=0.f,Q=0.f;
    #pragma unroll
    for(int w=0;w<8;w++){S+=rs[w];Q+=rq[w];}
    float mu=S/(float)Dm, var=Q/(float)Dm-mu*mu, rstd=rsqrtf(var+1e-5f);
    float* po=out+(LL)row*Dm;
    #pragma unroll
    for(int hf=0;hf<2;hf++){
        int c0=hf*1024+tid*4;
        float4 vv=hf?b4:a;
        float4 g4=*(const float4*)&g[c0], bt=*(const float4*)&be[c0];
        float4 o4;
        o4.x=(vv.x-mu)*rstd*g4.x+bt.x; o4.y=(vv.y-mu)*rstd*g4.y+bt.y;
        o4.z=(vv.z-mu)*rstd*g4.z+bt.z; o4.w=(vv.w-mu)*rstd*g4.w+bt.w;
        *(float4*)&po[c0]=o4;
        if(HILO){LL ix=(LL)row*Dm+c0;
            split2(o4.x,&oh[ix],&ol[ix]);split2(o4.y,&oh[ix+1],&ol[ix+1]);
            split2(o4.z,&oh[ix+2],&ol[ix+2]);split2(o4.w,&oh[ix+3],&ol[ix+3]);}
    }
}

static inline int ssz(int BN){ return 2*(2*16384+2*BN*128); }

extern "C" void kernel_launch(void* const* d_in, const int* in_sizes, int n_in, void* d_out, int out_size)
{
    const float* x=(const float*)d_in[0];
    const float* W_dq=(const float*)d_in[1];
    const float* W_uq=(const float*)d_in[2];
    const float* W_dkv=(const float*)d_in[3];
    const float* W_uk=(const float*)d_in[4];
    const float* W_uv=(const float*)d_in[5];
    const float* omega=(const float*)d_in[6];
    const float* W_o=(const float*)d_in[7];
    const float* ln1g=(const float*)d_in[8];
    const float* ln1b=(const float*)d_in[9];
    const float* gW=(const float*)d_in[10];
    const float* uW=(const float*)d_in[11];
    const float* dW=(const float*)d_in[12];
    const float* ln2g=(const float*)d_in[13];
    const float* ln2b=(const float*)d_in[14];
    float* out=(float*)d_out;

    #define GA(T,p,s) T* p; cudaGetSymbolAddress((void**)&p, s)
    GA(__half,xh,g_xh); GA(__half,xl,g_xl);
    GA(__half,cqh,g_cqh); GA(__half,cql,g_cql); GA(__half,ckvh,g_ckvh); GA(__half,ckvl,g_ckvl);
    GA(float,q,g_q); GA(float,kk,g_k); GA(float,vv,g_v);
    GA(__half,pqh,g_phiqh); GA(__half,pql,g_phiql); GA(float,pk,g_phik);
    GA(float,kvp,g_kvpart); GA(float,zp,g_zpart);
    GA(__half,kvh,g_kvTh); GA(__half,kvl,g_kvTl);
    GA(float,z,g_z); GA(float,num,g_num);
    GA(__half,ath,g_attnh); GA(__half,atl,g_attnl);
    GA(float,t1,g_t1); GA(float,hb,g_h);
    GA(__half,hh,g_hh); GA(__half,hl,g_hl);
    GA(float,silu,g_silu); GA(__half,acth,g_acth); GA(__half,actl,g_actl);
    GA(__half,w1h,g_w1h); GA(__half,w1l,g_w1l); GA(__half,w2h,g_w2h); GA(__half,w2l,g_w2l);
    GA(__half,w3h,g_w3h); GA(__half,w3l,g_w3l); GA(__half,w4h,g_w4h); GA(__half,w4l,g_w4l);
    GA(__half,w5h,g_w5h); GA(__half,w5l,g_w5l); GA(__half,w6h,g_w6h); GA(__half,w6l,g_w6l);
    GA(__half,w7h,g_w7h); GA(__half,w7l,g_w7l); GA(__half,w8h,g_w8h); GA(__half,w8l,g_w8l);
    GA(__half,w9h,g_w9h); GA(__half,w9l,g_w9l);
    #undef GA

    cudaFuncSetAttribute(tgemm<64,0,2>,  cudaFuncAttributeMaxDynamicSharedMemorySize, ssz(64));
    cudaFuncSetAttribute(tgemm<128,0,1>, cudaFuncAttributeMaxDynamicSharedMemorySize, ssz(128));
    cudaFuncSetAttribute(tgemm<128,1,1>, cudaFuncAttributeMaxDynamicSharedMemorySize, ssz(128));
    cudaFuncSetAttribute(tgemm<128,2,1>, cudaFuncAttributeMaxDynamicSharedMemorySize, ssz(128));
    cudaFuncSetAttribute(tgemm<128,3,2>, cudaFuncAttributeMaxDynamicSharedMemorySize, ssz(128));

    dim3 cb(32,8);
    convT<<<dim3(Rr/32,Dm/32),cb>>>(W_dq,w1h,w1l,Dm,Rr);
    convT<<<dim3(Rr/32,Dm/32),cb>>>(W_dkv,w2h,w2l,Dm,Rr);
    convT<<<dim3(Dm/32,Rr/32),cb>>>(W_uq,w3h,w3l,Rr,Dm);
    convT<<<dim3(HKV*DH/32,Rr/32),cb>>>(W_uk,w4h,w4l,Rr,HKV*DH);
    convT<<<dim3(HKV*DH/32,Rr/32),cb>>>(W_uv,w5h,w5l,Rr,HKV*DH);
    convT<<<dim3(Dm/32,Dm/32),cb>>>(W_o,w6h,w6l,Dm,Dm);
    convT<<<dim3(DFF/32,Dm/32),cb>>>(gW,w7h,w7l,Dm,DFF);
    convT<<<dim3(DFF/32,Dm/32),cb>>>(uW,w8h,w8l,Dm,DFF);
    convT<<<dim3(Dm/32,DFF/32),cb>>>(dW,w9h,w9l,DFF,Dm);
    convE<<<(int)(((LL)Mtok*Dm/4+255)/256),256>>>(x,xh,xl,(LL)Mtok*Dm);

    tgemm<64,0,2><<<dim3(1,Mtok/128),256,ssz(64)>>>(xh,xl,w1h,w1l,nullptr,nullptr,cqh,cql,Dm,Rr,0,0,0);
    tgemm<64,0,2><<<dim3(1,Mtok/128),256,ssz(64)>>>(xh,xl,w2h,w2l,nullptr,nullptr,ckvh,ckvl,Dm,Rr,0,0,0);
    tgemm<128,0,1><<<dim3(Dm/128,Mtok/128),256,ssz(128)>>>(cqh,cql,w3h,w3l,nullptr,q,nullptr,nullptr,Rr,Dm,0,0,0);
    tgemm<128,0,1><<<dim3(HKV*DH/128,Mtok/128),256,ssz(128)>>>(ckvh,ckvl,w4h,w4l,nullptr,kk,nullptr,nullptr,Rr,HKV*DH,0,0,0);
    tgemm<128,0,1><<<dim3(HKV*DH/128,Mtok/128),256,ssz(128)>>>(ckvh,ckvl,w5h,w5l,nullptr,vv,nullptr,nullptr,Rr,HKV*DH,0,0,0);

    phi_kernel<true><<<dim3(Mtok/16,Hh),256>>>(q,omega,nullptr,pqh,pql,Hh,Dm);
    phi_kernel<false><<<dim3(Mtok/16,HKV),256>>>(kk,omega,pk,nullptr,nullptr,HKV,HKV*DH);

    kv_split<<<dim3(32,1,32),256>>>(pk,vv,kvp);
    z_split<<<dim3(32,32),128>>>(pk,zp);
    kv_reduce<<<dim3(Ff*DH/128,64),128>>>(kvp,kvh,kvl);
    z_reduce<<<32,128>>>(zp,z);

    tgemm<128,0,1><<<dim3(1,Ss/128,64),256,ssz(128)>>>(pqh,pql,kvh,kvl,nullptr,num,nullptr,nullptr,Ff,DH,(LL)Ss*Ff,(LL)DH*Ff,(LL)Ss*DH);
    divide_k<<<dim3(Ss/32,64),128>>>(pqh,pql,z,num,ath,atl);

    tgemm<128,1,1><<<dim3(Dm/128,Mtok/128),256,ssz(128)>>>(ath,atl,w6h,w6l,x,t1,nullptr,nullptr,Dm,Dm,0,0,0);
    ln_k<true><<<Mtok,256>>>(t1,ln1g,ln1b,hb,hh,hl);

    tgemm<128,2,1><<<dim3(DFF/128,Mtok/128),256,ssz(128)>>>(hh,hl,w8h,w8l,nullptr,silu,nullptr,nullptr,Dm,DFF,0,0,0);
    tgemm<128,3,2><<<dim3(DFF/128,Mtok/128),256,ssz(128)>>>(hh,hl,w7h,w7l,silu,nullptr,acth,actl,Dm,DFF,0,0,0);
    tgemm<128,1,1><<<dim3(Dm/128,Mtok/128),256,ssz(128)>>>(acth,actl,w9h,w9l,hb,t1,nullptr,nullptr,DFF,Dm,0,0,0);
    ln_k<false><<<Mtok,256>>>(t1,ln2g,ln2b,out,nullptr,nullptr);
}

// round 9
// speedup vs baseline: 3.8797x; 1.3926x over previous
#include <cuda_runtime.h>
#include <cuda_fp16.h>
#include <cstdint>
#include <math.h>
typedef long long LL;

constexpr int Bb=4, Ss=4096, Dm=2048, DFF=8192, Hh=16, HKV=8, DH=128, Rr=64, KD=64, Ff=128;
constexpr int Mtok=Bb*Ss;

__device__ __forceinline__ uint32_t smem_u32(const void* p){uint32_t a;asm("{ .reg .u64 t; cvta.to.shared.u64 t, %1; cvt.u32.u64 %0, t; }":"=r"(a):"l"(p));return a;}
#define SW128(o) ((o) ^ (((o) >> 3) & 0x70))
#define CPA16(dst,src) asm volatile("cp.async.cg.shared.global [%0], [%1], 16;"::"r"(dst),"l"(src):"memory")
#define CPCOMMIT() asm volatile("cp.async.commit_group;":::"memory")
#define CPWAIT(n) asm volatile("cp.async.wait_group %0;"::"n"(n):"memory")
__device__ __forceinline__ void ldsm4(uint32_t* r, uint32_t a){
    asm volatile("ldmatrix.sync.aligned.m8n8.x4.shared.b16 {%0,%1,%2,%3}, [%4];"
        :"=r"(r[0]),"=r"(r[1]),"=r"(r[2]),"=r"(r[3]):"r"(a));}
#define MMA(d,a,b) asm volatile("mma.sync.aligned.m16n8k16.row.col.f32.f16.f16.f32 {%0,%1,%2,%3},{%4,%5,%6,%7},{%8,%9},{%0,%1,%2,%3};" \
  :"+f"((d)[0]),"+f"((d)[1]),"+f"((d)[2]),"+f"((d)[3]) \
  :"r"((a)[0]),"r"((a)[1]),"r"((a)[2]),"r"((a)[3]),"r"((b)[0]),"r"((b)[1]))

__device__ __align__(16) __half g_xh[(LL)Mtok*Dm];
__device__ __align__(16) __half g_xl[(LL)Mtok*Dm];
__device__ __align__(16) __half g_cqh[(LL)Mtok*Rr];
__device__ __align__(16) __half g_cql[(LL)Mtok*Rr];
__device__ __align__(16) __half g_ckvh[(LL)Mtok*Rr];
__device__ __align__(16) __half g_ckvl[(LL)Mtok*Rr];
__device__ __align__(16) float g_q[(LL)Mtok*Dm];
__device__ __align__(16) float g_k[(LL)Mtok*HKV*DH];
__device__ __align__(16) float g_v[(LL)Mtok*HKV*DH];
__device__ __align__(16) __half g_phiqh[(LL)Mtok*Hh*Ff];
__device__ __align__(16) __half g_phiql[(LL)Mtok*Hh*Ff];
__device__ __align__(16) float g_phik[(LL)Mtok*HKV*Ff];
__device__ __align__(16) float g_kvpart[(LL)32*32*Ff*DH];
__device__ __align__(16) float g_zpart[(LL)32*32*Ff];
__device__ __align__(16) __half g_kvTh[(LL)64*DH*Ff];
__device__ __align__(16) __half g_kvTl[(LL)64*DH*Ff];
__device__ __align__(16) float g_z[(LL)32*Ff];
__device__ __align__(16) float g_num[(LL)64*Ss*Ff];
__device__ __align__(16) __half g_attnh[(LL)Mtok*Dm];
__device__ __align__(16) float g_t1[(LL)Mtok*Dm];
__device__ __align__(16) float g_h[(LL)Mtok*Dm];
__device__ __align__(16) __half g_hh[(LL)Mtok*Dm];
__device__ __align__(16) float g_silu[(LL)Mtok*DFF];
__device__ __align__(16) __half g_acth[(LL)Mtok*DFF];
__device__ __align__(16) __half g_w1h[(LL)Rr*Dm];
__device__ __align__(16) __half g_w1l[(LL)Rr*Dm];
__device__ __align__(16) __half g_w2h[(LL)Rr*Dm];
__device__ __align__(16) __half g_w2l[(LL)Rr*Dm];
__device__ __align__(16) __half g_w3h[(LL)Dm*Rr];
__device__ __align__(16) __half g_w3l[(LL)Dm*Rr];
__device__ __align__(16) __half g_w4h[(LL)HKV*DH*Rr];
__device__ __align__(16) __half g_w4l[(LL)HKV*DH*Rr];
__device__ __align__(16) __half g_w5h[(LL)HKV*DH*Rr];
__device__ __align__(16) __half g_w5l[(LL)HKV*DH*Rr];
__device__ __align__(16) __half g_w6h[(LL)Dm*Dm];
__device__ __align__(16) __half g_w6l[(LL)Dm*Dm];
__device__ __align__(16) __half g_w7h[(LL)DFF*Dm];
__device__ __align__(16) __half g_w7l[(LL)DFF*Dm];
__device__ __align__(16) __half g_w8h[(LL)DFF*Dm];
__device__ __align__(16) __half g_w8l[(LL)DFF*Dm];
__device__ __align__(16) __half g_w9h[(LL)Dm*DFF];
__device__ __align__(16) __half g_w9l[(LL)Dm*DFF];

__device__ __forceinline__ void split2(float v, __half* ph, __half* pl){
    __half h=__float2half_rn(v); *ph=h; *pl=__float2half_rn(v-__half2float(h));}

__global__ __launch_bounds__(256) void convT(const float* __restrict__ W, __half* __restrict__ Wh, __half* __restrict__ Wl, int K, int N){
    __shared__ float t[32][33];
    int tx=threadIdx.x, ty=threadIdx.y, k0=blockIdx.y*32, n0=blockIdx.x*32;
    #pragma unroll
    for(int i=0;i<4;i++){int r=ty+i*8; t[r][tx]=W[(LL)(k0+r)*N+n0+tx];}
    __syncthreads();
    #pragma unroll
    for(int i=0;i<4;i++){int r=ty+i*8; LL o=(LL)(n0+r)*K+k0+tx; split2(t[tx][r],&Wh[o],&Wl[o]);}
}
__global__ __launch_bounds__(256) void convE(const float* __restrict__ X, __half* __restrict__ Xh, __half* __restrict__ Xl, LL n){
    LL i=((LL)blockIdx.x*256+threadIdx.x)*4; if(i>=n) return;
    float4 v=*(const float4*)&X[i];
    split2(v.x,&Xh[i],&Xl[i]); split2(v.y,&Xh[i+1],&Xl[i+1]); split2(v.z,&Xh[i+2],&Xl[i+2]); split2(v.w,&Xh[i+3],&Xl[i+3]);
}

// C[M,N]=A[M,K]@B[N,K]^T. PH=3: AhBh+AhBl+AlBh; PH=2: AhBh+AhBl (A hi only).
// EPI: 0 none,1 +D,2 silu,3 *D.  OUTM: 1 fp32 C, 2 fp16 Chi+Clo, 4 fp16 Chi only.
template<int BN,int PH,int EPI,int OUTM>
__global__ __launch_bounds__(256) void tgemm(
    const __half* __restrict__ Ah, const __half* __restrict__ Al,
    const __half* __restrict__ Bh, const __half* __restrict__ Bl,
    const float* __restrict__ D, float* __restrict__ C,
    __half* __restrict__ Chi, __half* __restrict__ Clo,
    int K, int ldc, LL sA, LL sB, LL sC)
{
    extern __shared__ char smem[];
    const uint32_t sbase=smem_u32(smem);
    const int tid=threadIdx.x, wid=tid>>5, lane=tid&31;
    constexpr int ABYT=16384, BBYT=BN*128, NA=(PH==3)?2:1, BOFF=NA*ABYT, BUF=BOFF+2*BBYT;
    const int bm=blockIdx.y*128, bn=blockIdx.x*BN, bz=blockIdx.z;
    const __half* APh=Ah+(LL)bz*sA+(LL)bm*K;
    const __half* APl=(PH==3)?(Al+(LL)bz*sA+(LL)bm*K):nullptr;
    const __half* BPh=Bh+(LL)bz*sB+(LL)bn*K;
    const __half* BPl=Bl+(LL)bz*sB+(LL)bn*K;
    const int KT=K>>6;

    auto load=[&](int kt,int buf){
        uint32_t base=sbase+buf*BUF;
        const LL ko=(LL)kt*64;
        #pragma unroll
        for(int i=0;i<4;i++){
            int c=tid+i*256, r=c>>3, ch=c&7; uint32_t sw=SW128(r*128+ch*16);
            CPA16(base+sw, APh+(LL)r*K+ko+ch*8);
            if(PH==3) CPA16(base+ABYT+sw, APl+(LL)r*K+ko+ch*8);
        }
        #pragma unroll
        for(int i=0;i<BN/32;i++){
            int c=tid+i*256, r=c>>3, ch=c&7; uint32_t sw=SW128(r*128+ch*16);
            CPA16(base+BOFF+sw,      BPh+(LL)r*K+ko+ch*8);
            CPA16(base+BOFF+BBYT+sw, BPl+(LL)r*K+ko+ch*8);
        }
    };

    constexpr int WN=BN/4, NF=WN/8;
    const int g=lane>>2, tg=lane&3, wm=wid&1, wn=wid>>1;
    float acc[4][NF][4];
    #pragma unroll
    for(int i=0;i<4;i++)
        #pragma unroll
        for(int j=0;j<NF;j++){acc[i][j][0]=0.f;acc[i][j][1]=0.f;acc[i][j][2]=0.f;acc[i][j][3]=0.f;}

    const int aquad=lane>>3, alr=lane&7;
    const int arow = wm*64 + ((aquad&1)<<3) + alr;   // + mf*16
    const int acol = (aquad>>1)<<4;                   // + ks*32
    const int brow2 = wn*WN + ((lane>>4)&1)*8 + (lane&7);  // + np*16
    const int bcol  = ((lane>>3)&1)<<4;               // + ks*32

    load(0,0); CPCOMMIT();
    for(int kt=0;kt<KT;kt++){
        if(kt+1<KT){ load(kt+1,(kt+1)&1); CPCOMMIT(); CPWAIT(1); }
        else { CPWAIT(0); }
        __syncthreads();
        const uint32_t cbase=sbase+(kt&1)*BUF;
        #pragma unroll
        for(int ks=0;ks<4;ks++){
            uint32_t ahf[4][4], alf[4][4], bhf[NF][2], blf[NF][2];
            #pragma unroll
            for(int mf=0;mf<4;mf++){
                uint32_t ad=cbase+SW128((arow+mf*16)*128 + ks*32+acol);
                ldsm4(ahf[mf], ad);
                if(PH==3) ldsm4(alf[mf], ad+ABYT);
            }
            #pragma unroll
            for(int np=0;np<NF/2;np++){
                uint32_t bd=cbase+BOFF+SW128((brow2+np*16)*128 + ks*32+bcol);
                uint32_t t4[4];
                ldsm4(t4,bd);
                bhf[2*np][0]=t4[0];bhf[2*np][1]=t4[1];bhf[2*np+1][0]=t4[2];bhf[2*np+1][1]=t4[3];
                ldsm4(t4,bd+BBYT);
                blf[2*np][0]=t4[0];blf[2*np][1]=t4[1];blf[2*np+1][0]=t4[2];blf[2*np+1][1]=t4[3];
            }
            #pragma unroll
            for(int mf=0;mf<4;mf++)
                #pragma unroll
                for(int nf=0;nf<NF;nf++){
                    MMA(acc[mf][nf], ahf[mf], bhf[nf]);
                    MMA(acc[mf][nf], ahf[mf], blf[nf]);
                    if(PH==3) MMA(acc[mf][nf], alf[mf], bhf[nf]);
                }
        }
        __syncthreads();
    }

    #pragma unroll
    for(int mf=0;mf<4;mf++)
        #pragma unroll
        for(int nf=0;nf<NF;nf++)
            #pragma unroll
            for(int hr=0;hr<2;hr++){
                int r=bm+wm*64+mf*16+g+hr*8;
                int c=bn+wn*WN+nf*8+tg*2;
                LL idx=(LL)bz*sC+(LL)r*ldc+c;
                float v0=acc[mf][nf][hr*2], v1=acc[mf][nf][hr*2+1];
                if(EPI==1){float2 d2=*(const float2*)&D[idx]; v0+=d2.x; v1+=d2.y;}
                else if(EPI==2){v0=v0/(1.f+expf(-v0)); v1=v1/(1.f+expf(-v1));}
                else if(EPI==3){float2 d2=*(const float2*)&D[idx]; v0*=d2.x; v1*=d2.y;}
                if(OUTM&1){float2 o2; o2.x=v0; o2.y=v1; *(float2*)&C[idx]=o2;}
                if(OUTM&2){
                    __half h0=__float2half_rn(v0), h1=__float2half_rn(v1);
                    *(__half2*)&Chi[idx]=__halves2half2(h0,h1);
                    *(__half2*)&Clo[idx]=__halves2half2(
                        __float2half_rn(v0-__half2float(h0)), __float2half_rn(v1-__half2float(h1)));
                }
                if(OUTM&4){
                    *(__half2*)&Chi[idx]=__halves2half2(__float2half_rn(v0),__float2half_rn(v1));
                }
            }
}

template<bool HILO>
__global__ __launch_bounds__(256) void phi_kernel(const float* __restrict__ qk, const float* __restrict__ omega,
    float* __restrict__ phi, __half* __restrict__ ph, __half* __restrict__ pl, int nheads, int estride)
{
    __shared__ float om[DH][KD]; __shared__ float qs[16][DH];
    const int h=blockIdx.y, t0=blockIdx.x*16, tid=threadIdx.x;
    #pragma unroll
    for(int i=0;i<8;i++){int fi=tid+i*256,d=fi>>4,c4=(fi&15)*4;*(float4*)&om[d][c4]=*(const float4*)&omega[d*KD+c4];}
    #pragma unroll
    for(int i=0;i<2;i++){int fi=tid+i*256,r=fi>>5,c4=(fi&31)*4;*(float4*)&qs[r][c4]=*(const float4*)&qk[(LL)(t0+r)*estride+h*DH+c4];}
    __syncthreads();
    const int tl=tid>>4, kg=(tid&15)*4, t=t0+tl, b=t/Ss, sr=t-b*Ss;
    const LL base=((LL)(b*nheads+h)*Ss+sr)*Ff;
    #pragma unroll
    for(int kk=0;kk<4;kk++){
        int kc=kg+kk; float pr=0.f;
        #pragma unroll
        for(int d=0;d<DH;d++) pr+=qs[tl][d]*om[d][kc];
        float sv,cv; sincosf(pr,&sv,&cv);
        float vc=cv*0.125f, vs=sv*0.125f;
        if(HILO){split2(vc,&ph[base+kc],&pl[base+kc]); split2(vs,&ph[base+KD+kc],&pl[base+KD+kc]);}
        else{phi[base+kc]=vc; phi[base+KD+kc]=vs;}
    }
}

__global__ __launch_bounds__(256) void kv_split(const float* __restrict__ phik, const float* __restrict__ v, float* __restrict__ kvpart){
    const int split=blockIdx.x, bh2=blockIdx.z, b=bh2>>3, hk=bh2&7;
    const float* Pk=phik+(LL)bh2*Ss*Ff;
    const float* V=v+(LL)b*Ss*(HKV*DH)+hk*DH;
    __shared__ float As[16][128]; __shared__ float Bs[16][128];
    const int tid=threadIdx.x, tc=tid&15, tr=tid>>4, lr=tid>>5, lc=(tid&31)<<2;
    float acc[8][8];
    #pragma unroll
    for(int i=0;i<8;i++)
        #pragma unroll
        for(int j=0;j<8;j++) acc[i][j]=0.f;
    for(int ks=0;ks<8;ks++){
        int s0=split*128+ks*16;
        #pragma unroll
        for(int pp=0;pp<2;pp++){int r=lr+pp*8;
            *(float4*)&As[r][lc]=*(const float4*)&Pk[(LL)(s0+r)*Ff+lc];
            *(float4*)&Bs[r][lc]=*(const float4*)&V[(LL)(s0+r)*(HKV*DH)+lc];}
        __syncthreads();
        #pragma unroll
        for(int kk=0;kk<16;kk++){
            float ar[8],br[8];
            *(float4*)&ar[0]=*(const float4*)&As[kk][tr*8]; *(float4*)&ar[4]=*(const float4*)&As[kk][tr*8+4];
            *(float4*)&br[0]=*(const float4*)&Bs[kk][tc*8]; *(float4*)&br[4]=*(const float4*)&Bs[kk][tc*8+4];
            #pragma unroll
            for(int i=0;i<8;i++)
                #pragma unroll
                for(int j=0;j<8;j++) acc[i][j]+=ar[i]*br[j];
        }
        __syncthreads();
    }
    float* o=kvpart+((LL)bh2*32+split)*(Ff*DH);
    #pragma unroll
    for(int i=0;i<8;i++)
        #pragma unroll
        for(int j=0;j<8;j++) o[(tr*8+i)*DH+tc*8+j]=acc[i][j];
}
__global__ void z_split(const float* __restrict__ phik, float* __restrict__ zp){
    const int split=blockIdx.x, bh2=blockIdx.y, f=threadIdx.x;
    const float* P=phik+(LL)bh2*Ss*Ff; float s=0.f;
    for(int i=0;i<128;i++) s+=P[(LL)(split*128+i)*Ff+f];
    zp[((LL)bh2*32+split)*Ff+f]=s;
}
__global__ void kv_reduce(const float* __restrict__ kvp, __half* __restrict__ kvh, __half* __restrict__ kvl){
    const int bh=blockIdx.y, bh2=(bh>>4)*8+((bh&15)>>1);
    const int idx=blockIdx.x*128+threadIdx.x;
    const float* p=kvp+(LL)bh2*32*(Ff*DH)+idx;
    float s=0.f;
    #pragma unroll
    for(int sp=0;sp<32;sp++) s+=p[(LL)sp*(Ff*DH)];
    int f=idx>>7, d=idx&127;
    LL o=(LL)bh*(DH*Ff)+(LL)d*Ff+f;
    split2(s,&kvh[o],&kvl[o]);
}
__global__ void z_reduce(const float* __restrict__ zp, float* __restrict__ z){
    const int bh2=blockIdx.x, f=threadIdx.x; float s=0.f;
    #pragma unroll
    for(int sp=0;sp<32;sp++) s+=zp[((LL)bh2*32+sp)*Ff+f];
    z[bh2*Ff+f]=s;
}
__global__ __launch_bounds__(128) void divide_k(const __half* __restrict__ pqh, const __half* __restrict__ pql,
    const float* __restrict__ z, const float* __restrict__ num, __half* __restrict__ ah){
    const int chunk=blockIdx.x, bh=blockIdx.y, tid=threadIdx.x;
    const int b=bh>>4, h=bh&15, bh2=b*8+(h>>1);
    __shared__ float zs[128]; __shared__ float red[4];
    zs[tid]=z[bh2*Ff+tid]; __syncthreads();
    for(int i=0;i<32;i++){
        int s=chunk*32+i;
        LL off=((LL)bh*Ss+s)*Ff+tid;
        float pq=__half2float(pqh[off])+__half2float(pql[off]);
        float pv=pq*zs[tid];
        #pragma unroll
        for(int o=16;o>0;o>>=1) pv+=__shfl_down_sync(0xffffffffu,pv,o);
        if((tid&31)==0) red[tid>>5]=pv;
        __syncthreads();
        float den=red[0]+red[1]+red[2]+red[3];
        float a=num[off]/(den+1e-6f);
        ah[((LL)(b*Ss+s))*Dm+h*DH+tid]=__float2half_rn(a);
        __syncthreads();
    }
}
template<bool HILO>
__global__ __launch_bounds__(256) void ln_k(const float* __restrict__ in, const float* __restrict__ g, const float* __restrict__ be,
    float* __restrict__ out, __half* __restrict__ oh){
    const int row=blockIdx.x, tid=threadIdx.x;
    const float* p=in+(LL)row*Dm;
    float4 a=*(const float4*)&p[tid*4], b4=*(const float4*)&p[1024+tid*4];
    float s=a.x+a.y+a.z+a.w+b4.x+b4.y+b4.z+b4.w;
    float q=a.x*a.x+a.y*a.y+a.z*a.z+a.w*a.w+b4.x*b4.x+b4.y*b4.y+b4.z*b4.z+b4.w*b4.w;
    __shared__ float rs[8], rq[8];
    #pragma unroll
    for(int o=16;o>0;o>>=1){s+=__shfl_down_sync(0xffffffffu,s,o);q+=__shfl_down_sync(0xffffffffu,q,o);}
    if((tid&31)==0){rs[tid>>5]=s;rq[tid>>5]=q;}
    __syncthreads();
    float S=0.f,Q=0.f;
    #pragma unroll
    for(int w=0;w<8;w++){S+=rs[w];Q+=rq[w];}
    float mu=S/(float)Dm, var=Q/(float)Dm-mu*mu, rstd=rsqrtf(var+1e-5f);
    float* po=out+(LL)row*Dm;
    #pragma unroll
    for(int hf=0;hf<2;hf++){
        int c0=hf*1024+tid*4;
        float4 vv=hf?b4:a;
        float4 g4=*(const float4*)&g[c0], bt=*(const float4*)&be[c0];
        float4 o4;
        o4.x=(vv.x-mu)*rstd*g4.x+bt.x; o4.y=(vv.y-mu)*rstd*g4.y+bt.y;
        o4.z=(vv.z-mu)*rstd*g4.z+bt.z; o4.w=(vv.w-mu)*rstd*g4.w+bt.w;
        *(float4*)&po[c0]=o4;
        if(HILO){LL ix=(LL)row*Dm+c0;
            *(__half2*)&oh[ix]  =__halves2half2(__float2half_rn(o4.x),__float2half_rn(o4.y));
            *(__half2*)&oh[ix+2]=__halves2half2(__float2half_rn(o4.z),__float2half_rn(o4.w));}
    }
}

static inline int ssz(int BN,int PH){ return 2*(((PH==3)?2:1)*16384 + 2*BN*128); }

extern "C" void kernel_launch(void* const* d_in, const int* in_sizes, int n_in, void* d_out, int out_size)
{
    const float* x=(const float*)d_in[0];
    const float* W_dq=(const float*)d_in[1];
    const float* W_uq=(const float*)d_in[2];
    const float* W_dkv=(const float*)d_in[3];
    const float* W_uk=(const float*)d_in[4];
    const float* W_uv=(const float*)d_in[5];
    const float* omega=(const float*)d_in[6];
    const float* W_o=(const float*)d_in[7];
    const float* ln1g=(const float*)d_in[8];
    const float* ln1b=(const float*)d_in[9];
    const float* gW=(const float*)d_in[10];
    const float* uW=(const float*)d_in[11];
    const float* dW=(const float*)d_in[12];
    const float* ln2g=(const float*)d_in[13];
    const float* ln2b=(const float*)d_in[14];
    float* out=(float*)d_out;

    #define GA(T,p,s) T* p; cudaGetSymbolAddress((void**)&p, s)
    GA(__half,xh,g_xh); GA(__half,xl,g_xl);
    GA(__half,cqh,g_cqh); GA(__half,cql,g_cql); GA(__half,ckvh,g_ckvh); GA(__half,ckvl,g_ckvl);
    GA(float,q,g_q); GA(float,kk,g_k); GA(float,vv,g_v);
    GA(__half,pqh,g_phiqh); GA(__half,pql,g_phiql); GA(float,pk,g_phik);
    GA(float,kvp,g_kvpart); GA(float,zp,g_zpart);
    GA(__half,kvh,g_kvTh); GA(__half,kvl,g_kvTl);
    GA(float,z,g_z); GA(float,num,g_num);
    GA(__half,ath,g_attnh);
    GA(float,t1,g_t1); GA(float,hb,g_h);
    GA(__half,hh,g_hh);
    GA(float,silu,g_silu); GA(__half,acth,g_acth);
    GA(__half,w1h,g_w1h); GA(__half,w1l,g_w1l); GA(__half,w2h,g_w2h); GA(__half,w2l,g_w2l);
    GA(__half,w3h,g_w3h); GA(__half,w3l,g_w3l); GA(__half,w4h,g_w4h); GA(__half,w4l,g_w4l);
    GA(__half,w5h,g_w5h); GA(__half,w5l,g_w5l); GA(__half,w6h,g_w6h); GA(__half,w6l,g_w6l);
    GA(__half,w7h,g_w7h); GA(__half,w7l,g_w7l); GA(__half,w8h,g_w8h); GA(__half,w8l,g_w8l);
    GA(__half,w9h,g_w9h); GA(__half,w9l,g_w9l);
    #undef GA

    cudaFuncSetAttribute(tgemm<64,3,0,2>,  cudaFuncAttributeMaxDynamicSharedMemorySize, ssz(64,3));
    cudaFuncSetAttribute(tgemm<128,3,0,1>, cudaFuncAttributeMaxDynamicSharedMemorySize, ssz(128,3));
    cudaFuncSetAttribute(tgemm<128,2,1,1>, cudaFuncAttributeMaxDynamicSharedMemorySize, ssz(128,2));
    cudaFuncSetAttribute(tgemm<256,2,2,1>, cudaFuncAttributeMaxDynamicSharedMemorySize, ssz(256,2));
    cudaFuncSetAttribute(tgemm<256,2,3,4>, cudaFuncAttributeMaxDynamicSharedMemorySize, ssz(256,2));

    dim3 cb(32,8);
    convT<<<dim3(Rr/32,Dm/32),cb>>>(W_dq,w1h,w1l,Dm,Rr);
    convT<<<dim3(Rr/32,Dm/32),cb>>>(W_dkv,w2h,w2l,Dm,Rr);
    convT<<<dim3(Dm/32,Rr/32),cb>>>(W_uq,w3h,w3l,Rr,Dm);
    convT<<<dim3(HKV*DH/32,Rr/32),cb>>>(W_uk,w4h,w4l,Rr,HKV*DH);
    convT<<<dim3(HKV*DH/32,Rr/32),cb>>>(W_uv,w5h,w5l,Rr,HKV*DH);
    convT<<<dim3(Dm/32,Dm/32),cb>>>(W_o,w6h,w6l,Dm,Dm);
    convT<<<dim3(DFF/32,Dm/32),cb>>>(gW,w7h,w7l,Dm,DFF);
    convT<<<dim3(DFF/32,Dm/32),cb>>>(uW,w8h,w8l,Dm,DFF);
    convT<<<dim3(Dm/32,DFF/32),cb>>>(dW,w9h,w9l,DFF,Dm);
    convE<<<(int)(((LL)Mtok*Dm/4+255)/256),256>>>(x,xh,xl,(LL)Mtok*Dm);

    tgemm<64,3,0,2><<<dim3(1,Mtok/128),256,ssz(64,3)>>>(xh,xl,w1h,w1l,nullptr,nullptr,cqh,cql,Dm,Rr,0,0,0);
    tgemm<64,3,0,2><<<dim3(1,Mtok/128),256,ssz(64,3)>>>(xh,xl,w2h,w2l,nullptr,nullptr,ckvh,ckvl,Dm,Rr,0,0,0);
    tgemm<128,3,0,1><<<dim3(Dm/128,Mtok/128),256,ssz(128,3)>>>(cqh,cql,w3h,w3l,nullptr,q,nullptr,nullptr,Rr,Dm,0,0,0);
    tgemm<128,3,0,1><<<dim3(HKV*DH/128,Mtok/128),256,ssz(128,3)>>>(ckvh,ckvl,w4h,w4l,nullptr,kk,nullptr,nullptr,Rr,HKV*DH,0,0,0);
    tgemm<128,3,0,1><<<dim3(HKV*DH/128,Mtok/128),256,ssz(128,3)>>>(ckvh,ckvl,w5h,w5l,nullptr,vv,nullptr,nullptr,Rr,HKV*DH,0,0,0);

    phi_kernel<true><<<dim3(Mtok/16,Hh),256>>>(q,omega,nullptr,pqh,pql,Hh,Dm);
    phi_kernel<false><<<dim3(Mtok/16,HKV),256>>>(kk,omega,pk,nullptr,nullptr,HKV,HKV*DH);

    kv_split<<<dim3(32,1,32),256>>>(pk,vv,kvp);
    z_split<<<dim3(32,32),128>>>(pk,zp);
    kv_reduce<<<dim3(Ff*DH/128,64),128>>>(kvp,kvh,kvl);
    z_reduce<<<32,128>>>(zp,z);

    tgemm<128,3,0,1><<<dim3(1,Ss/128,64),256,ssz(128,3)>>>(pqh,pql,kvh,kvl,nullptr,num,nullptr,nullptr,Ff,DH,(LL)Ss*Ff,(LL)DH*Ff,(LL)Ss*DH);
    divide_k<<<dim3(Ss/32,64),128>>>(pqh,pql,z,num,ath);

    tgemm<128,2,1,1><<<dim3(Dm/128,Mtok/128),256,ssz(128,2)>>>(ath,nullptr,w6h,w6l,x,t1,nullptr,nullptr,Dm,Dm,0,0,0);
    ln_k<true><<<Mtok,256>>>(t1,ln1g,ln1b,hb,hh);

    tgemm<256,2,2,1><<<dim3(DFF/256,Mtok/128),256,ssz(256,2)>>>(hh,nullptr,w8h,w8l,nullptr,silu,nullptr,nullptr,Dm,DFF,0,0,0);
    tgemm<256,2,3,4><<<dim3(DFF/256,Mtok/128),256,ssz(256,2)>>>(hh,nullptr,w7h,w7l,silu,nullptr,acth,nullptr,Dm,DFF,0,0,0);
    tgemm<128,2,1,1><<<dim3(Dm/128,Mtok/128),256,ssz(128,2)>>>(acth,nullptr,w9h,w9l,hb,t1,nullptr,nullptr,DFF,Dm,0,0,0);
    ln_k<false><<<Mtok,256>>>(t1,ln2g,ln2b,out,nullptr);
}

// round 10
// speedup vs baseline: 4.0459x; 1.0428x over previous
#include <cuda_runtime.h>
#include <cuda_fp16.h>
#include <cstdint>
#include <math.h>
typedef long long LL;

constexpr int Bb=4, Ss=4096, Dm=2048, DFF=8192, Hh=16, HKV=8, DH=128, Rr=64, KD=64, Ff=128;
constexpr int Mtok=Bb*Ss;

__device__ __forceinline__ uint32_t smem_u32(const void* p){uint32_t a;asm("{ .reg .u64 t; cvta.to.shared.u64 t, %1; cvt.u32.u64 %0, t; }":"=r"(a):"l"(p));return a;}
#define SW128(o) ((o) ^ (((o) >> 3) & 0x70))
#define CPA16(dst,src) asm volatile("cp.async.cg.shared.global [%0], [%1], 16;"::"r"(dst),"l"(src):"memory")
#define CPCOMMIT() asm volatile("cp.async.commit_group;":::"memory")
#define CPWAIT(n) asm volatile("cp.async.wait_group %0;"::"n"(n):"memory")
__device__ __forceinline__ void ldsm4(uint32_t* r, uint32_t a){
    asm volatile("ldmatrix.sync.aligned.m8n8.x4.shared.b16 {%0,%1,%2,%3}, [%4];"
        :"=r"(r[0]),"=r"(r[1]),"=r"(r[2]),"=r"(r[3]):"r"(a));}
#define MMA(d,a,b) asm volatile("mma.sync.aligned.m16n8k16.row.col.f32.f16.f16.f32 {%0,%1,%2,%3},{%4,%5,%6,%7},{%8,%9},{%0,%1,%2,%3};" \
  :"+f"((d)[0]),"+f"((d)[1]),"+f"((d)[2]),"+f"((d)[3]) \
  :"r"((a)[0]),"r"((a)[1]),"r"((a)[2]),"r"((a)[3]),"r"((b)[0]),"r"((b)[1]))

__device__ __align__(16) __half g_xh[(LL)Mtok*Dm];
__device__ __align__(16) __half g_xl[(LL)Mtok*Dm];
__device__ __align__(16) __half g_cqh[(LL)Mtok*Rr];
__device__ __align__(16) __half g_cql[(LL)Mtok*Rr];
__device__ __align__(16) __half g_ckvh[(LL)Mtok*Rr];
__device__ __align__(16) __half g_ckvl[(LL)Mtok*Rr];
__device__ __align__(16) float g_q[(LL)Mtok*Dm];
__device__ __align__(16) float g_k[(LL)Mtok*HKV*DH];
__device__ __align__(16) float g_v[(LL)Mtok*HKV*DH];
__device__ __align__(16) __half g_phiqh[(LL)Mtok*Hh*Ff];
__device__ __align__(16) __half g_phiql[(LL)Mtok*Hh*Ff];
__device__ __align__(16) float g_phik[(LL)Mtok*HKV*Ff];
__device__ __align__(16) float g_kvpart[(LL)32*32*Ff*DH];
__device__ __align__(16) float g_zpart[(LL)32*32*Ff];
__device__ __align__(16) __half g_kvTh[(LL)64*DH*Ff];
__device__ __align__(16) __half g_kvTl[(LL)64*DH*Ff];
__device__ __align__(16) float g_z[(LL)32*Ff];
__device__ __align__(16) float g_num[(LL)64*Ss*Ff];
__device__ __align__(16) __half g_attnh[(LL)Mtok*Dm];
__device__ __align__(16) float g_t1[(LL)Mtok*Dm];
__device__ __align__(16) float g_h[(LL)Mtok*Dm];
__device__ __align__(16) __half g_hh[(LL)Mtok*Dm];
__device__ __align__(16) __half g_acth[(LL)Mtok*DFF];
__device__ __align__(16) __half g_w1h[(LL)Rr*Dm];
__device__ __align__(16) __half g_w1l[(LL)Rr*Dm];
__device__ __align__(16) __half g_w2h[(LL)Rr*Dm];
__device__ __align__(16) __half g_w2l[(LL)Rr*Dm];
__device__ __align__(16) __half g_w3h[(LL)Dm*Rr];
__device__ __align__(16) __half g_w3l[(LL)Dm*Rr];
__device__ __align__(16) __half g_w4h[(LL)HKV*DH*Rr];
__device__ __align__(16) __half g_w4l[(LL)HKV*DH*Rr];
__device__ __align__(16) __half g_w5h[(LL)HKV*DH*Rr];
__device__ __align__(16) __half g_w5l[(LL)HKV*DH*Rr];
__device__ __align__(16) __half g_w6h[(LL)Dm*Dm];
__device__ __align__(16) __half g_w6l[(LL)Dm*Dm];
__device__ __align__(16) __half g_w7h[(LL)DFF*Dm];
__device__ __align__(16) __half g_w7l[(LL)DFF*Dm];
__device__ __align__(16) __half g_w8h[(LL)DFF*Dm];
__device__ __align__(16) __half g_w8l[(LL)DFF*Dm];
__device__ __align__(16) __half g_w9h[(LL)Dm*DFF];
__device__ __align__(16) __half g_w9l[(LL)Dm*DFF];

__device__ __forceinline__ void split2(float v, __half* ph, __half* pl){
    __half h=__float2half_rn(v); *ph=h; *pl=__float2half_rn(v-__half2float(h));}

__global__ __launch_bounds__(256) void convT(const float* __restrict__ W, __half* __restrict__ Wh, __half* __restrict__ Wl, int K, int N){
    __shared__ float t[32][33];
    int tx=threadIdx.x, ty=threadIdx.y, k0=blockIdx.y*32, n0=blockIdx.x*32;
    #pragma unroll
    for(int i=0;i<4;i++){int r=ty+i*8; t[r][tx]=W[(LL)(k0+r)*N+n0+tx];}
    __syncthreads();
    #pragma unroll
    for(int i=0;i<4;i++){int r=ty+i*8; LL o=(LL)(n0+r)*K+k0+tx; split2(t[tx][r],&Wh[o],&Wl[o]);}
}
__global__ __launch_bounds__(256) void convE(const float* __restrict__ X, __half* __restrict__ Xh, __half* __restrict__ Xl, LL n){
    LL i=((LL)blockIdx.x*256+threadIdx.x)*4; if(i>=n) return;
    float4 v=*(const float4*)&X[i];
    split2(v.x,&Xh[i],&Xl[i]); split2(v.y,&Xh[i+1],&Xl[i+1]); split2(v.z,&Xh[i+2],&Xl[i+2]); split2(v.w,&Xh[i+3],&Xl[i+3]);
}

// C[M,N]=A[M,K]@B[N,K]^T. PH=3: AhBh+AhBl+AlBh; PH=2: AhBh+AhBl (A hi only).
template<int BN,int PH,int EPI,int OUTM>
__global__ __launch_bounds__(256) void tgemm(
    const __half* __restrict__ Ah, const __half* __restrict__ Al,
    const __half* __restrict__ Bh, const __half* __restrict__ Bl,
    const float* __restrict__ D, float* __restrict__ C,
    __half* __restrict__ Chi, __half* __restrict__ Clo,
    int K, int ldc, LL sA, LL sB, LL sC)
{
    extern __shared__ char smem[];
    const uint32_t sbase=smem_u32(smem);
    const int tid=threadIdx.x, wid=tid>>5, lane=tid&31;
    constexpr int ABYT=16384, BBYT=BN*128, NA=(PH==3)?2:1, BOFF=NA*ABYT, BUF=BOFF+2*BBYT;
    const int bm=blockIdx.y*128, bn=blockIdx.x*BN, bz=blockIdx.z;
    const __half* APh=Ah+(LL)bz*sA+(LL)bm*K;
    const __half* APl=(PH==3)?(Al+(LL)bz*sA+(LL)bm*K):nullptr;
    const __half* BPh=Bh+(LL)bz*sB+(LL)bn*K;
    const __half* BPl=Bl+(LL)bz*sB+(LL)bn*K;
    const int KT=K>>6;

    auto load=[&](int kt,int buf){
        uint32_t base=sbase+buf*BUF;
        const LL ko=(LL)kt*64;
        #pragma unroll
        for(int i=0;i<4;i++){
            int c=tid+i*256, r=c>>3, ch=c&7; uint32_t sw=SW128(r*128+ch*16);
            CPA16(base+sw, APh+(LL)r*K+ko+ch*8);
            if(PH==3) CPA16(base+ABYT+sw, APl+(LL)r*K+ko+ch*8);
        }
        #pragma unroll
        for(int i=0;i<BN/32;i++){
            int c=tid+i*256, r=c>>3, ch=c&7; uint32_t sw=SW128(r*128+ch*16);
            CPA16(base+BOFF+sw,      BPh+(LL)r*K+ko+ch*8);
            CPA16(base+BOFF+BBYT+sw, BPl+(LL)r*K+ko+ch*8);
        }
    };

    constexpr int WN=BN/4, NF=WN/8;
    const int g=lane>>2, tg=lane&3, wm=wid&1, wn=wid>>1;
    float acc[4][NF][4];
    #pragma unroll
    for(int i=0;i<4;i++)
        #pragma unroll
        for(int j=0;j<NF;j++){acc[i][j][0]=0.f;acc[i][j][1]=0.f;acc[i][j][2]=0.f;acc[i][j][3]=0.f;}

    const int aquad=lane>>3, alr=lane&7;
    const int arow = wm*64 + ((aquad&1)<<3) + alr;
    const int acol = (aquad>>1)<<4;
    const int brow2 = wn*WN + ((lane>>4)&1)*8 + (lane&7);
    const int bcol  = ((lane>>3)&1)<<4;

    load(0,0); CPCOMMIT();
    for(int kt=0;kt<KT;kt++){
        if(kt+1<KT){ load(kt+1,(kt+1)&1); CPCOMMIT(); CPWAIT(1); }
        else { CPWAIT(0); }
        __syncthreads();
        const uint32_t cbase=sbase+(kt&1)*BUF;
        #pragma unroll
        for(int ks=0;ks<4;ks++){
            uint32_t ahf[4][4], alf[4][4], bhf[NF][2], blf[NF][2];
            #pragma unroll
            for(int mf=0;mf<4;mf++){
                uint32_t ad=cbase+SW128((arow+mf*16)*128 + ks*32+acol);
                ldsm4(ahf[mf], ad);
                if(PH==3) ldsm4(alf[mf], ad+ABYT);
            }
            #pragma unroll
            for(int np=0;np<NF/2;np++){
                uint32_t bd=cbase+BOFF+SW128((brow2+np*16)*128 + ks*32+bcol);
                uint32_t t4[4];
                ldsm4(t4,bd);
                bhf[2*np][0]=t4[0];bhf[2*np][1]=t4[1];bhf[2*np+1][0]=t4[2];bhf[2*np+1][1]=t4[3];
                ldsm4(t4,bd+BBYT);
                blf[2*np][0]=t4[0];blf[2*np][1]=t4[1];blf[2*np+1][0]=t4[2];blf[2*np+1][1]=t4[3];
            }
            #pragma unroll
            for(int mf=0;mf<4;mf++)
                #pragma unroll
                for(int nf=0;nf<NF;nf++){
                    MMA(acc[mf][nf], ahf[mf], bhf[nf]);
                    MMA(acc[mf][nf], ahf[mf], blf[nf]);
                    if(PH==3) MMA(acc[mf][nf], alf[mf], bhf[nf]);
                }
        }
        __syncthreads();
    }

    #pragma unroll
    for(int mf=0;mf<4;mf++)
        #pragma unroll
        for(int nf=0;nf<NF;nf++)
            #pragma unroll
            for(int hr=0;hr<2;hr++){
                int r=bm+wm*64+mf*16+g+hr*8;
                int c=bn+wn*WN+nf*8+tg*2;
                LL idx=(LL)bz*sC+(LL)r*ldc+c;
                float v0=acc[mf][nf][hr*2], v1=acc[mf][nf][hr*2+1];
                if(EPI==1){float2 d2=*(const float2*)&D[idx]; v0+=d2.x; v1+=d2.y;}
                if(OUTM&1){float2 o2; o2.x=v0; o2.y=v1; *(float2*)&C[idx]=o2;}
                if(OUTM&2){
                    __half h0=__float2half_rn(v0), h1=__float2half_rn(v1);
                    *(__half2*)&Chi[idx]=__halves2half2(h0,h1);
                    *(__half2*)&Clo[idx]=__halves2half2(
                        __float2half_rn(v0-__half2float(h0)), __float2half_rn(v1-__half2float(h1)));
                }
                if(OUTM&4){
                    *(__half2*)&Chi[idx]=__halves2half2(__float2half_rn(v0),__float2half_rn(v1));
                }
            }
}

// Fused gate+up: act = (A@Wg^T) * silu(A@Wu^T). BM=256, BN=64 per weight, PH2, K=Dm.
__global__ __launch_bounds__(256) void tgemm2(
    const __half* __restrict__ Ah,
    const __half* __restrict__ Bgh, const __half* __restrict__ Bgl,
    const __half* __restrict__ Buh, const __half* __restrict__ Bul,
    __half* __restrict__ Co)
{
    extern __shared__ char smem[];
    const uint32_t sbase=smem_u32(smem);
    const int tid=threadIdx.x, wid=tid>>5, lane=tid&31;
    constexpr int ABYT=32768, BBYT=8192, BUF=ABYT+4*BBYT;  // 65536
    const int bm=blockIdx.y*256, bn=blockIdx.x*64;
    const __half* AP=Ah+(LL)bm*Dm;
    const __half* Bg[2]={Bgh+(LL)bn*Dm, Bgl+(LL)bn*Dm};
    const __half* Bu[2]={Buh+(LL)bn*Dm, Bul+(LL)bn*Dm};
    const int KT=Dm>>6;

    auto load=[&](int kt,int buf){
        uint32_t base=sbase+buf*BUF;
        const LL ko=(LL)kt*64;
        #pragma unroll
        for(int i=0;i<8;i++){
            int c=tid+i*256, r=c>>3, ch=c&7; uint32_t sw=SW128(r*128+ch*16);
            CPA16(base+sw, AP+(LL)r*Dm+ko+ch*8);
        }
        #pragma unroll
        for(int i=0;i<2;i++){
            int c=tid+i*256, r=c>>3, ch=c&7; uint32_t sw=SW128(r*128+ch*16);
            CPA16(base+ABYT+sw,        Bg[0]+(LL)r*Dm+ko+ch*8);
            CPA16(base+ABYT+BBYT+sw,   Bg[1]+(LL)r*Dm+ko+ch*8);
            CPA16(base+ABYT+2*BBYT+sw, Bu[0]+(LL)r*Dm+ko+ch*8);
            CPA16(base+ABYT+3*BBYT+sw, Bu[1]+(LL)r*Dm+ko+ch*8);
        }
    };

    const int g=lane>>2, tg=lane&3, wm=wid&3, wn=wid>>2;  // 4x2 warp grid, tile 64x32
    float accg[4][4][4], accu[4][4][4];
    #pragma unroll
    for(int i=0;i<4;i++)
        #pragma unroll
        for(int j=0;j<4;j++)
            #pragma unroll
            for(int e=0;e<4;e++){accg[i][j][e]=0.f;accu[i][j][e]=0.f;}

    const int aquad=lane>>3, alr=lane&7;
    const int arow = wm*64 + ((aquad&1)<<3) + alr;
    const int acol = (aquad>>1)<<4;
    const int brow2 = wn*32 + ((lane>>4)&1)*8 + (lane&7);
    const int bcol  = ((lane>>3)&1)<<4;

    load(0,0); CPCOMMIT();
    for(int kt=0;kt<KT;kt++){
        if(kt+1<KT){ load(kt+1,(kt+1)&1); CPCOMMIT(); CPWAIT(1); }
        else { CPWAIT(0); }
        __syncthreads();
        const uint32_t cbase=sbase+(kt&1)*BUF;
        #pragma unroll
        for(int ks=0;ks<4;ks++){
            uint32_t ahf[4][4], bgh[4][2], bgl[4][2], buh[4][2], bul[4][2];
            #pragma unroll
            for(int mf=0;mf<4;mf++)
                ldsm4(ahf[mf], cbase+SW128((arow+mf*16)*128 + ks*32+acol));
            #pragma unroll
            for(int np=0;np<2;np++){
                uint32_t bd=cbase+ABYT+SW128((brow2+np*16)*128 + ks*32+bcol);
                uint32_t t4[4];
                ldsm4(t4,bd);        bgh[2*np][0]=t4[0];bgh[2*np][1]=t4[1];bgh[2*np+1][0]=t4[2];bgh[2*np+1][1]=t4[3];
                ldsm4(t4,bd+BBYT);   bgl[2*np][0]=t4[0];bgl[2*np][1]=t4[1];bgl[2*np+1][0]=t4[2];bgl[2*np+1][1]=t4[3];
                ldsm4(t4,bd+2*BBYT); buh[2*np][0]=t4[0];buh[2*np][1]=t4[1];buh[2*np+1][0]=t4[2];buh[2*np+1][1]=t4[3];
                ldsm4(t4,bd+3*BBYT); bul[2*np][0]=t4[0];bul[2*np][1]=t4[1];bul[2*np+1][0]=t4[2];bul[2*np+1][1]=t4[3];
            }
            #pragma unroll
            for(int mf=0;mf<4;mf++)
                #pragma unroll
                for(int nf=0;nf<4;nf++){
                    MMA(accg[mf][nf], ahf[mf], bgh[nf]);
                    MMA(accg[mf][nf], ahf[mf], bgl[nf]);
                    MMA(accu[mf][nf], ahf[mf], buh[nf]);
                    MMA(accu[mf][nf], ahf[mf], bul[nf]);
                }
        }
        __syncthreads();
    }

    #pragma unroll
    for(int mf=0;mf<4;mf++)
        #pragma unroll
        for(int nf=0;nf<4;nf++)
            #pragma unroll
            for(int hr=0;hr<2;hr++){
                int r=bm+wm*64+mf*16+g+hr*8;
                int c=bn+wn*32+nf*8+tg*2;
                LL idx=(LL)r*DFF+c;
                float g0=accg[mf][nf][hr*2], g1=accg[mf][nf][hr*2+1];
                float u0=accu[mf][nf][hr*2], u1=accu[mf][nf][hr*2+1];
                float a0=g0*(u0/(1.f+expf(-u0))), a1=g1*(u1/(1.f+expf(-u1)));
                *(__half2*)&Co[idx]=__halves2half2(__float2half_rn(a0),__float2half_rn(a1));
            }
}

template<bool HILO>
__global__ __launch_bounds__(256) void phi_kernel(const float* __restrict__ qk, const float* __restrict__ omega,
    float* __restrict__ phi, __half* __restrict__ ph, __half* __restrict__ pl, int nheads, int estride)
{
    __shared__ float om[DH][KD]; __shared__ float qs[16][DH];
    const int h=blockIdx.y, t0=blockIdx.x*16, tid=threadIdx.x;
    #pragma unroll
    for(int i=0;i<8;i++){int fi=tid+i*256,d=fi>>4,c4=(fi&15)*4;*(float4*)&om[d][c4]=*(const float4*)&omega[d*KD+c4];}
    #pragma unroll
    for(int i=0;i<2;i++){int fi=tid+i*256,r=fi>>5,c4=(fi&31)*4;*(float4*)&qs[r][c4]=*(const float4*)&qk[(LL)(t0+r)*estride+h*DH+c4];}
    __syncthreads();
    const int tl=tid>>4, kg=(tid&15)*4, t=t0+tl, b=t/Ss, sr=t-b*Ss;
    const LL base=((LL)(b*nheads+h)*Ss+sr)*Ff;
    #pragma unroll
    for(int kk=0;kk<4;kk++){
        int kc=kg+kk; float pr=0.f;
        #pragma unroll
        for(int d=0;d<DH;d++) pr+=qs[tl][d]*om[d][kc];
        float sv,cv; sincosf(pr,&sv,&cv);
        float vc=cv*0.125f, vs=sv*0.125f;
        if(HILO){split2(vc,&ph[base+kc],&pl[base+kc]); split2(vs,&ph[base+KD+kc],&pl[base+KD+kc]);}
        else{phi[base+kc]=vc; phi[base+KD+kc]=vs;}
    }
}

__global__ __launch_bounds__(256) void kv_split(const float* __restrict__ phik, const float* __restrict__ v, float* __restrict__ kvpart){
    const int split=blockIdx.x, bh2=blockIdx.z, b=bh2>>3, hk=bh2&7;
    const float* Pk=phik+(LL)bh2*Ss*Ff;
    const float* V=v+(LL)b*Ss*(HKV*DH)+hk*DH;
    __shared__ float As[16][128]; __shared__ float Bs[16][128];
    const int tid=threadIdx.x, tc=tid&15, tr=tid>>4, lr=tid>>5, lc=(tid&31)<<2;
    float acc[8][8];
    #pragma unroll
    for(int i=0;i<8;i++)
        #pragma unroll
        for(int j=0;j<8;j++) acc[i][j]=0.f;
    for(int ks=0;ks<8;ks++){
        int s0=split*128+ks*16;
        #pragma unroll
        for(int pp=0;pp<2;pp++){int r=lr+pp*8;
            *(float4*)&As[r][lc]=*(const float4*)&Pk[(LL)(s0+r)*Ff+lc];
            *(float4*)&Bs[r][lc]=*(const float4*)&V[(LL)(s0+r)*(HKV*DH)+lc];}
        __syncthreads();
        #pragma unroll
        for(int kk=0;kk<16;kk++){
            float ar[8],br[8];
            *(float4*)&ar[0]=*(const float4*)&As[kk][tr*8]; *(float4*)&ar[4]=*(const float4*)&As[kk][tr*8+4];
            *(float4*)&br[0]=*(const float4*)&Bs[kk][tc*8]; *(float4*)&br[4]=*(const float4*)&Bs[kk][tc*8+4];
            #pragma unroll
            for(int i=0;i<8;i++)
                #pragma unroll
                for(int j=0;j<8;j++) acc[i][j]+=ar[i]*br[j];
        }
        __syncthreads();
    }
    float* o=kvpart+((LL)bh2*32+split)*(Ff*DH);
    #pragma unroll
    for(int i=0;i<8;i++)
        #pragma unroll
        for(int j=0;j<8;j++) o[(tr*8+i)*DH+tc*8+j]=acc[i][j];
}
__global__ void z_split(const float* __restrict__ phik, float* __restrict__ zp){
    const int split=blockIdx.x, bh2=blockIdx.y, f=threadIdx.x;
    const float* P=phik+(LL)bh2*Ss*Ff; float s=0.f;
    for(int i=0;i<128;i++) s+=P[(LL)(split*128+i)*Ff+f];
    zp[((LL)bh2*32+split)*Ff+f]=s;
}
__global__ void kv_reduce(const float* __restrict__ kvp, __half* __restrict__ kvh, __half* __restrict__ kvl){
    const int bh=blockIdx.y, bh2=(bh>>4)*8+((bh&15)>>1);
    const int idx=blockIdx.x*128+threadIdx.x;
    const float* p=kvp+(LL)bh2*32*(Ff*DH)+idx;
    float s=0.f;
    #pragma unroll
    for(int sp=0;sp<32;sp++) s+=p[(LL)sp*(Ff*DH)];
    int f=idx>>7, d=idx&127;
    LL o=(LL)bh*(DH*Ff)+(LL)d*Ff+f;
    split2(s,&kvh[o],&kvl[o]);
}
__global__ void z_reduce(const float* __restrict__ zp, float* __restrict__ z){
    const int bh2=blockIdx.x, f=threadIdx.x; float s=0.f;
    #pragma unroll
    for(int sp=0;sp<32;sp++) s+=zp[((LL)bh2*32+sp)*Ff+f];
    z[bh2*Ff+f]=s;
}
__global__ __launch_bounds__(128) void divide_k(const __half* __restrict__ pqh, const __half* __restrict__ pql,
    const float* __restrict__ z, const float* __restrict__ num, __half* __restrict__ ah){
    const int chunk=blockIdx.x, bh=blockIdx.y, tid=threadIdx.x;
    const int b=bh>>4, h=bh&15, bh2=b*8+(h>>1);
    __shared__ float zs[128]; __shared__ float red[4];
    zs[tid]=z[bh2*Ff+tid]; __syncthreads();
    for(int i=0;i<32;i++){
        int s=chunk*32+i;
        LL off=((LL)bh*Ss+s)*Ff+tid;
        float pq=__half2float(pqh[off])+__half2float(pql[off]);
        float pv=pq*zs[tid];
        #pragma unroll
        for(int o=16;o>0;o>>=1) pv+=__shfl_down_sync(0xffffffffu,pv,o);
        if((tid&31)==0) red[tid>>5]=pv;
        __syncthreads();
        float den=red[0]+red[1]+red[2]+red[3];
        float a=num[off]/(den+1e-6f);
        ah[((LL)(b*Ss+s))*Dm+h*DH+tid]=__float2half_rn(a);
        __syncthreads();
    }
}
template<bool HILO>
__global__ __launch_bounds__(256) void ln_k(const float* __restrict__ in, const float* __restrict__ g, const float* __restrict__ be,
    float* __restrict__ out, __half* __restrict__ oh){
    const int row=blockIdx.x, tid=threadIdx.x;
    const float* p=in+(LL)row*Dm;
    float4 a=*(const float4*)&p[tid*4], b4=*(const float4*)&p[1024+tid*4];
    float s=a.x+a.y+a.z+a.w+b4.x+b4.y+b4.z+b4.w;
    float q=a.x*a.x+a.y*a.y+a.z*a.z+a.w*a.w+b4.x*b4.x+b4.y*b4.y+b4.z*b4.z+b4.w*b4.w;
    __shared__ float rs[8], rq[8];
    #pragma unroll
    for(int o=16;o>0;o>>=1){s+=__shfl_down_sync(0xffffffffu,s,o);q+=__shfl_down_sync(0xffffffffu,q,o);}
    if((tid&31)==0){rs[tid>>5]=s;rq[tid>>5]=q;}
    __syncthreads();
    float S=0.f,Q=0.f;
    #pragma unroll
    for(int w=0;w<8;w++){S+=rs[w];Q+=rq[w];}
    float mu=S/(float)Dm, var=Q/(float)Dm-mu*mu, rstd=rsqrtf(var+1e-5f);
    float* po=out+(LL)row*Dm;
    #pragma unroll
    for(int hf=0;hf<2;hf++){
        int c0=hf*1024+tid*4;
        float4 vv=hf?b4:a;
        float4 g4=*(const float4*)&g[c0], bt=*(const float4*)&be[c0];
        float4 o4;
        o4.x=(vv.x-mu)*rstd*g4.x+bt.x; o4.y=(vv.y-mu)*rstd*g4.y+bt.y;
        o4.z=(vv.z-mu)*rstd*g4.z+bt.z; o4.w=(vv.w-mu)*rstd*g4.w+bt.w;
        *(float4*)&po[c0]=o4;
        if(HILO){LL ix=(LL)row*Dm+c0;
            *(__half2*)&oh[ix]  =__halves2half2(__float2half_rn(o4.x),__float2half_rn(o4.y));
            *(__half2*)&oh[ix+2]=__halves2half2(__float2half_rn(o4.z),__float2half_rn(o4.w));}
    }
}

static inline int ssz(int BN,int PH){ return 2*(((PH==3)?2:1)*16384 + 2*BN*128); }

extern "C" void kernel_launch(void* const* d_in, const int* in_sizes, int n_in, void* d_out, int out_size)
{
    const float* x=(const float*)d_in[0];
    const float* W_dq=(const float*)d_in[1];
    const float* W_uq=(const float*)d_in[2];
    const float* W_dkv=(const float*)d_in[3];
    const float* W_uk=(const float*)d_in[4];
    const float* W_uv=(const float*)d_in[5];
    const float* omega=(const float*)d_in[6];
    const float* W_o=(const float*)d_in[7];
    const float* ln1g=(const float*)d_in[8];
    const float* ln1b=(const float*)d_in[9];
    const float* gW=(const float*)d_in[10];
    const float* uW=(const float*)d_in[11];
    const float* dW=(const float*)d_in[12];
    const float* ln2g=(const float*)d_in[13];
    const float* ln2b=(const float*)d_in[14];
    float* out=(float*)d_out;

    #define GA(T,p,s) T* p; cudaGetSymbolAddress((void**)&p, s)
    GA(__half,xh,g_xh); GA(__half,xl,g_xl);
    GA(__half,cqh,g_cqh); GA(__half,cql,g_cql); GA(__half,ckvh,g_ckvh); GA(__half,ckvl,g_ckvl);
    GA(float,q,g_q); GA(float,kk,g_k); GA(float,vv,g_v);
    GA(__half,pqh,g_phiqh); GA(__half,pql,g_phiql); GA(float,pk,g_phik);
    GA(float,kvp,g_kvpart); GA(float,zp,g_zpart);
    GA(__half,kvh,g_kvTh); GA(__half,kvl,g_kvTl);
    GA(float,z,g_z); GA(float,num,g_num);
    GA(__half,ath,g_attnh);
    GA(float,t1,g_t1); GA(float,hb,g_h);
    GA(__half,hh,g_hh);
    GA(__half,acth,g_acth);
    GA(__half,w1h,g_w1h); GA(__half,w1l,g_w1l); GA(__half,w2h,g_w2h); GA(__half,w2l,g_w2l);
    GA(__half,w3h,g_w3h); GA(__half,w3l,g_w3l); GA(__half,w4h,g_w4h); GA(__half,w4l,g_w4l);
    GA(__half,w5h,g_w5h); GA(__half,w5l,g_w5l); GA(__half,w6h,g_w6h); GA(__half,w6l,g_w6l);
    GA(__half,w7h,g_w7h); GA(__half,w7l,g_w7l); GA(__half,w8h,g_w8h); GA(__half,w8l,g_w8l);
    GA(__half,w9h,g_w9h); GA(__half,w9l,g_w9l);
    #undef GA

    cudaFuncSetAttribute(tgemm<64,3,0,2>,  cudaFuncAttributeMaxDynamicSharedMemorySize, ssz(64,3));
    cudaFuncSetAttribute(tgemm<128,3,0,1>, cudaFuncAttributeMaxDynamicSharedMemorySize, ssz(128,3));
    cudaFuncSetAttribute(tgemm<256,2,1,1>, cudaFuncAttributeMaxDynamicSharedMemorySize, ssz(256,2));
    cudaFuncSetAttribute(tgemm2, cudaFuncAttributeMaxDynamicSharedMemorySize, 131072);

    dim3 cb(32,8);
    // order chosen so ncu (-s 5) lands on a mainloop tgemm (idx 5 = ckv)
    convT<<<dim3(Rr/32,Dm/32),cb>>>(W_dq,w1h,w1l,Dm,Rr);                    // 0
    convT<<<dim3(Rr/32,Dm/32),cb>>>(W_dkv,w2h,w2l,Dm,Rr);                   // 1
    convE<<<(int)(((LL)Mtok*Dm/4+255)/256),256>>>(x,xh,xl,(LL)Mtok*Dm);     // 2
    tgemm<64,3,0,2><<<dim3(1,Mtok/128),256,ssz(64,3)>>>(xh,xl,w1h,w1l,nullptr,nullptr,cqh,cql,Dm,Rr,0,0,0); // 3
    convT<<<dim3(Dm/32,Rr/32),cb>>>(W_uq,w3h,w3l,Rr,Dm);                    // 4
    tgemm<64,3,0,2><<<dim3(1,Mtok/128),256,ssz(64,3)>>>(xh,xl,w2h,w2l,nullptr,nullptr,ckvh,ckvl,Dm,Rr,0,0,0); // 5 <- ncu
    convT<<<dim3(HKV*DH/32,Rr/32),cb>>>(W_uk,w4h,w4l,Rr,HKV*DH);
    convT<<<dim3(HKV*DH/32,Rr/32),cb>>>(W_uv,w5h,w5l,Rr,HKV*DH);
    convT<<<dim3(Dm/32,Dm/32),cb>>>(W_o,w6h,w6l,Dm,Dm);
    convT<<<dim3(DFF/32,Dm/32),cb>>>(gW,w7h,w7l,Dm,DFF);
    convT<<<dim3(DFF/32,Dm/32),cb>>>(uW,w8h,w8l,Dm,DFF);
    convT<<<dim3(Dm/32,DFF/32),cb>>>(dW,w9h,w9l,DFF,Dm);

    tgemm<128,3,0,1><<<dim3(Dm/128,Mtok/128),256,ssz(128,3)>>>(cqh,cql,w3h,w3l,nullptr,q,nullptr,nullptr,Rr,Dm,0,0,0);
    tgemm<128,3,0,1><<<dim3(HKV*DH/128,Mtok/128),256,ssz(128,3)>>>(ckvh,ckvl,w4h,w4l,nullptr,kk,nullptr,nullptr,Rr,HKV*DH,0,0,0);
    tgemm<128,3,0,1><<<dim3(HKV*DH/128,Mtok/128),256,ssz(128,3)>>>(ckvh,ckvl,w5h,w5l,nullptr,vv,nullptr,nullptr,Rr,HKV*DH,0,0,0);

    phi_kernel<true><<<dim3(Mtok/16,Hh),256>>>(q,omega,nullptr,pqh,pql,Hh,Dm);
    phi_kernel<false><<<dim3(Mtok/16,HKV),256>>>(kk,omega,pk,nullptr,nullptr,HKV,HKV*DH);

    kv_split<<<dim3(32,1,32),256>>>(pk,vv,kvp);
    z_split<<<dim3(32,32),128>>>(pk,zp);
    kv_reduce<<<dim3(Ff*DH/128,64),128>>>(kvp,kvh,kvl);
    z_reduce<<<32,128>>>(zp,z);

    tgemm<128,3,0,1><<<dim3(1,Ss/128,64),256,ssz(128,3)>>>(pqh,pql,kvh,kvl,nullptr,num,nullptr,nullptr,Ff,DH,(LL)Ss*Ff,(LL)DH*Ff,(LL)Ss*DH);
    divide_k<<<dim3(Ss/32,64),128>>>(pqh,pql,z,num,ath);

    tgemm<256,2,1,1><<<dim3(Dm/256,Mtok/128),256,ssz(256,2)>>>(ath,nullptr,w6h,w6l,x,t1,nullptr,nullptr,Dm,Dm,0,0,0);
    ln_k<true><<<Mtok,256>>>(t1,ln1g,ln1b,hb,hh);

    tgemm2<<<dim3(DFF/64,Mtok/256),256,131072>>>(hh,w7h,w7l,w8h,w8l,acth);
    tgemm<256,2,1,1><<<dim3(Dm/256,Mtok/128),256,ssz(256,2)>>>(acth,nullptr,w9h,w9l,hb,t1,nullptr,nullptr,DFF,Dm,0,0,0);
    ln_k<false><<<Mtok,256>>>(t1,ln2g,ln2b,out,nullptr);
}